// round 9
// baseline (speedup 1.0000x reference)
#include <cuda_runtime.h>
#include <cuda_bf16.h>
#include <cstdint>
#include <math.h>

#define N_TOK 4096
#define DM 1024
#define NHEADS 16
#define DH 64

// ---------------------------------------------------------------------------
// Scratch (allocation-free rule: __device__ globals)
// ---------------------------------------------------------------------------
__device__ float g_q[N_TOK * DM];
__device__ float g_k[N_TOK * DM];
__device__ float g_v[N_TOK * DM];

__device__ __nv_bfloat16 g_xh[N_TOK * DM];
__device__ __nv_bfloat16 g_xl[N_TOK * DM];
__device__ __nv_bfloat16 g_oh[N_TOK * DM];
__device__ __nv_bfloat16 g_ol[N_TOK * DM];
__device__ __nv_bfloat16 g_wth[4 * DM * DM];  // W^T hi: [w][n][k]
__device__ __nv_bfloat16 g_wtl[4 * DM * DM];  // W^T lo
// normalized/split attention operands, [head][tok][64]
__device__ __nv_bfloat16 g_qh[N_TOK * DM];
__device__ __nv_bfloat16 g_ql[N_TOK * DM];
__device__ __nv_bfloat16 g_kh[N_TOK * DM];
__device__ __nv_bfloat16 g_kl[N_TOK * DM];
__device__ __nv_bfloat16 g_vh[N_TOK * DM];
__device__ __nv_bfloat16 g_vl[N_TOK * DM];

#define SWZ64(o)  ((o) ^ (((o) >> 3) & 0x30))
#define SWZ128(o) ((o) ^ (((o) >> 3) & 0x70))

__device__ __forceinline__ uint32_t smem_u32(const void* p) {
    uint32_t a;
    asm("{ .reg .u64 t; cvta.to.shared.u64 t, %1; cvt.u32.u64 %0, t; }"
        : "=r"(a) : "l"(p));
    return a;
}
__device__ __forceinline__ void cpa16(uint32_t dst, const void* src) {
    asm volatile("cp.async.cg.shared.global [%0], [%1], 16;"
                 :: "r"(dst), "l"(src));
}
#define CPA_COMMIT() asm volatile("cp.async.commit_group;" ::: "memory")
#define CPA_WAIT0()  asm volatile("cp.async.wait_group 0;" ::: "memory")

__device__ __forceinline__ void ldsm4(uint32_t addr, uint32_t r[4]) {
    asm volatile("ldmatrix.sync.aligned.m8n8.x4.shared.b16 {%0,%1,%2,%3}, [%4];"
                 : "=r"(r[0]), "=r"(r[1]), "=r"(r[2]), "=r"(r[3]) : "r"(addr));
}
__device__ __forceinline__ void ldsm4t(uint32_t addr, uint32_t r[4]) {
    asm volatile("ldmatrix.sync.aligned.m8n8.x4.trans.shared.b16 {%0,%1,%2,%3}, [%4];"
                 : "=r"(r[0]), "=r"(r[1]), "=r"(r[2]), "=r"(r[3]) : "r"(addr));
}
__device__ __forceinline__ void ldsm2(uint32_t addr, uint32_t r[2]) {
    asm volatile("ldmatrix.sync.aligned.m8n8.x2.shared.b16 {%0,%1}, [%2];"
                 : "=r"(r[0]), "=r"(r[1]) : "r"(addr));
}
__device__ __forceinline__ void mma_bf16(float c[4], const uint32_t a[4],
                                         const uint32_t b[2]) {
    asm volatile(
        "mma.sync.aligned.m16n8k16.row.col.f32.bf16.bf16.f32 "
        "{%0,%1,%2,%3}, {%4,%5,%6,%7}, {%8,%9}, {%0,%1,%2,%3};"
        : "+f"(c[0]), "+f"(c[1]), "+f"(c[2]), "+f"(c[3])
        : "r"(a[0]), "r"(a[1]), "r"(a[2]), "r"(a[3]), "r"(b[0]), "r"(b[1]));
}
__device__ __forceinline__ uint32_t pack2(float a, float b) {
    uint32_t r;
    asm("cvt.rn.bf16x2.f32 %0, %1, %2;" : "=r"(r) : "f"(b), "f"(a));
    return r;
}
__device__ __forceinline__ float bfr(float x) {
    return __bfloat162float(__float2bfloat16(x));
}

// ---------------------------------------------------------------------------
// Split fp32 -> (hi, lo) bf16, elementwise (for x).
// ---------------------------------------------------------------------------
__global__ __launch_bounds__(256) void split_kernel(
    const float* __restrict__ src, __nv_bfloat16* __restrict__ h,
    __nv_bfloat16* __restrict__ l)
{
    int i = blockIdx.x * 256 + threadIdx.x;
    float4 v = ((const float4*)src)[i];
    ((uint32_t*)h)[2 * i + 0] = pack2(v.x, v.y);
    ((uint32_t*)h)[2 * i + 1] = pack2(v.z, v.w);
    ((uint32_t*)l)[2 * i + 0] = pack2(v.x - bfr(v.x), v.y - bfr(v.y));
    ((uint32_t*)l)[2 * i + 1] = pack2(v.z - bfr(v.z), v.w - bfr(v.w));
}

// ---------------------------------------------------------------------------
// Transpose + split all 4 weight matrices: out[w][n][k] = split(W_w[k][n]).
// ---------------------------------------------------------------------------
__global__ __launch_bounds__(256) void tsplit_kernel(
    const float* __restrict__ W0, const float* __restrict__ W1,
    const float* __restrict__ W2, const float* __restrict__ W3,
    __nv_bfloat16* __restrict__ H, __nv_bfloat16* __restrict__ L)
{
    const float* W = (blockIdx.z == 0) ? W0 : (blockIdx.z == 1) ? W1
                   : (blockIdx.z == 2) ? W2 : W3;
    __nv_bfloat16* h = H + (size_t)blockIdx.z * DM * DM;
    __nv_bfloat16* l = L + (size_t)blockIdx.z * DM * DM;
    __shared__ float t[32][33];
    const int bx = blockIdx.x * 32;
    const int by = blockIdx.y * 32;
    const int tx = threadIdx.x;
    for (int j = threadIdx.y; j < 32; j += 8)
        t[j][tx] = W[(size_t)(by + j) * DM + bx + tx];
    __syncthreads();
    for (int j = threadIdx.y; j < 32; j += 8) {
        float v = t[tx][j];
        __nv_bfloat16 hv = __float2bfloat16(v);
        __nv_bfloat16 lv = __float2bfloat16(v - __bfloat162float(hv));
        size_t idx = (size_t)(bx + j) * DM + by + tx;
        h[idx] = hv;
        l[idx] = lv;
    }
}

// ---------------------------------------------------------------------------
// Prep: q,k (l2norm) and v -> hi/lo bf16 in [head][tok][64] layout.
// ---------------------------------------------------------------------------
__global__ __launch_bounds__(256) void qkv_prep_kernel(
    const float* __restrict__ q, const float* __restrict__ k,
    const float* __restrict__ v,
    __nv_bfloat16* __restrict__ qh, __nv_bfloat16* __restrict__ ql,
    __nv_bfloat16* __restrict__ kh, __nv_bfloat16* __restrict__ kl,
    __nv_bfloat16* __restrict__ vh, __nv_bfloat16* __restrict__ vl)
{
    const int gwarp = blockIdx.x * 8 + (threadIdx.x >> 5);
    const int lane = threadIdx.x & 31;
    const int buf = gwarp >> 16;           // 0=q, 1=k, 2=v
    const int rem = gwarp & 0xFFFF;
    const int head = rem & 15, tok = rem >> 4;

    const float* src = (buf == 0) ? q : (buf == 1) ? k : v;
    __nv_bfloat16* dh = (buf == 0) ? qh : (buf == 1) ? kh : vh;
    __nv_bfloat16* dl = (buf == 0) ? ql : (buf == 1) ? kl : vl;

    float2 val = *(const float2*)&src[(size_t)tok * DM + head * DH + lane * 2];
    if (buf < 2) {
        float ss = val.x * val.x + val.y * val.y;
#pragma unroll
        for (int off = 16; off > 0; off >>= 1)
            ss += __shfl_xor_sync(0xffffffffu, ss, off);
        float inv = 1.0f / fmaxf(sqrtf(ss), 1e-12f);
        val.x *= inv;
        val.y *= inv;
    }
    const size_t di = ((size_t)head * N_TOK + tok) * DH + lane * 2;
    ((uint32_t*)dh)[di >> 1] = pack2(val.x, val.y);
    ((uint32_t*)dl)[di >> 1] = pack2(val.x - bfr(val.x), val.y - bfr(val.y));
}

// ---------------------------------------------------------------------------
// HMMA split-bf16 GEMM with cp.async double buffering.
// C[M x 1024] = A @ B^T. CTA 128x128, BK=32, 8 warps (2m x 4n).
// If NOUT == 3, blockIdx.z selects the weight slice and output buffer
// (merged q/k/v launch); NOUT == 1 is a plain single GEMM.
// ---------------------------------------------------------------------------
#define GEMM_SMEM (2 * 32768)

template <int NOUT>
__global__ __launch_bounds__(256, 2) void gemm_mma_kernel(
    const __nv_bfloat16* __restrict__ Ah, const __nv_bfloat16* __restrict__ Al,
    const __nv_bfloat16* __restrict__ Bh_, const __nv_bfloat16* __restrict__ Bl_,
    float* __restrict__ C0, float* __restrict__ C1, float* __restrict__ C2)
{
    extern __shared__ char sm[];
    const uint32_t sbase = smem_u32(sm);

    const int tid = threadIdx.x;
    const int wid = tid >> 5, lane = tid & 31;
    const int wm = wid & 1, wn = wid >> 1;
    const int m0 = blockIdx.y * 128, n0 = blockIdx.x * 128;

    const __nv_bfloat16* Bh = Bh_;
    const __nv_bfloat16* Bl = Bl_;
    float* C = C0;
    if (NOUT == 3) {
        const size_t woff = (size_t)blockIdx.z * DM * DM;
        Bh = Bh_ + woff;
        Bl = Bl_ + woff;
        C = (blockIdx.z == 0) ? C0 : (blockIdx.z == 1) ? C1 : C2;
    }

    const int a_row = ((lane >> 3) & 1) * 8 + (lane & 7);
    const int a_kb  = (lane >> 4) * 16;
    const int l15 = lane & 15;
    const int b_row = l15 & 7;
    const int b_kb  = (l15 >> 3) * 16;

    const int r_0 = tid >> 2, kb_0 = tid & 3;
    const int r_1 = (tid + 256) >> 2, kb_1 = (tid + 256) & 3;
    const uint32_t so_0 = SWZ64(r_0 * 64 + kb_0 * 16);
    const uint32_t so_1 = SWZ64(r_1 * 64 + kb_1 * 16);

    float c[4][4][4] = {};

#define GEMM_ISSUE(kc, s) do {                                                  \
    const int _k0 = (kc) * 32;                                                  \
    const uint32_t _b = sbase + (s) * 32768;                                    \
    const size_t _ga0 = (size_t)(m0 + r_0) * DM + _k0 + kb_0 * 8;               \
    const size_t _ga1 = (size_t)(m0 + r_1) * DM + _k0 + kb_1 * 8;               \
    const size_t _gb0 = (size_t)(n0 + r_0) * DM + _k0 + kb_0 * 8;               \
    const size_t _gb1 = (size_t)(n0 + r_1) * DM + _k0 + kb_1 * 8;               \
    cpa16(_b + so_0,             Ah + _ga0);                                    \
    cpa16(_b + so_1,             Ah + _ga1);                                    \
    cpa16(_b + 8192  + so_0,     Al + _ga0);                                    \
    cpa16(_b + 8192  + so_1,     Al + _ga1);                                    \
    cpa16(_b + 16384 + so_0,     Bh + _gb0);                                    \
    cpa16(_b + 16384 + so_1,     Bh + _gb1);                                    \
    cpa16(_b + 24576 + so_0,     Bl + _gb0);                                    \
    cpa16(_b + 24576 + so_1,     Bl + _gb1);                                    \
    CPA_COMMIT();                                                               \
} while (0)

    GEMM_ISSUE(0, 0);

    for (int kc = 0; kc < 32; kc++) {
        CPA_WAIT0();
        __syncthreads();
        if (kc < 31) GEMM_ISSUE(kc + 1, (kc + 1) & 1);

        const uint32_t uAh = sbase + (kc & 1) * 32768;
        const uint32_t uAl = uAh + 8192;
        const uint32_t uBh = uAh + 16384;
        const uint32_t uBl = uAh + 24576;

#pragma unroll
        for (int ks = 0; ks < 2; ks++) {
            uint32_t bh[4][2], bl[4][2];
#pragma unroll
            for (int nt = 0; nt < 4; nt++) {
                const uint32_t bo =
                    SWZ64((wn * 32 + nt * 8 + b_row) * 64 + ks * 32 + b_kb);
                ldsm2(uBh + bo, bh[nt]);
                ldsm2(uBl + bo, bl[nt]);
            }
#pragma unroll
            for (int mt = 0; mt < 4; mt++) {
                uint32_t ah[4], al[4];
                const uint32_t ao =
                    SWZ64((wm * 64 + mt * 16 + a_row) * 64 + ks * 32 + a_kb);
                ldsm4(uAh + ao, ah);
                ldsm4(uAl + ao, al);
#pragma unroll
                for (int nt = 0; nt < 4; nt++) {
                    mma_bf16(c[mt][nt], ah, bh[nt]);
                    mma_bf16(c[mt][nt], ah, bl[nt]);
                    mma_bf16(c[mt][nt], al, bh[nt]);
                }
            }
        }
        __syncthreads();
    }

    const int gq = lane >> 2, tq = lane & 3;
#pragma unroll
    for (int mt = 0; mt < 4; mt++) {
#pragma unroll
        for (int nt = 0; nt < 4; nt++) {
            const int row = m0 + wm * 64 + mt * 16 + gq;
            const int col = n0 + wn * 32 + nt * 8 + tq * 2;
            *(float2*)&C[(size_t)row * DM + col] =
                make_float2(c[mt][nt][0], c[mt][nt][1]);
            *(float2*)&C[(size_t)(row + 8) * DM + col] =
                make_float2(c[mt][nt][2], c[mt][nt][3]);
        }
    }
}

// ---------------------------------------------------------------------------
// Tensor-core causal flash attention, prepped bf16 inputs, cp.async
// double-buffered KV. Block = (q-tile 128, head), 8 warps (m16 each).
// 96KB dyn smem; __launch_bounds__(256,2) -> 2 CTAs/SM (192KB of 228KB).
// ---------------------------------------------------------------------------
#define ATTN_SMEM (32768 + 2 * 32768)

__global__ __launch_bounds__(256, 2) void attn_mma_kernel(
    const __nv_bfloat16* __restrict__ qh, const __nv_bfloat16* __restrict__ ql,
    const __nv_bfloat16* __restrict__ kh, const __nv_bfloat16* __restrict__ kl,
    const __nv_bfloat16* __restrict__ vh, const __nv_bfloat16* __restrict__ vl,
    __nv_bfloat16* __restrict__ oh, __nv_bfloat16* __restrict__ ol)
{
    extern __shared__ char sm[];
    const uint32_t sb = smem_u32(sm);
    const uint32_t uQh = sb, uQl = sb + 16384;

    const int tid = threadIdx.x, wid = tid >> 5, lane = tid & 31;
    const int h = blockIdx.y;
    const int qi = gridDim.x - 1 - blockIdx.x;
    const int q0 = qi * 128;
    const size_t hbase = (size_t)h * N_TOK * DH;  // bf16 elems

    // ---- load Q hi/lo tiles (each 128 rows x 128B), swizzled ----
    {
        const char* gqh = (const char*)(qh + hbase + (size_t)q0 * DH);
        const char* gql = (const char*)(ql + hbase + (size_t)q0 * DH);
#pragma unroll
        for (int it = 0; it < 4; it++) {
            int idx = tid + 256 * it;
            int row = idx >> 3, ck = idx & 7;
            uint32_t so = SWZ128(row * 128 + ck * 16);
            *(uint4*)(sm + so) = *(const uint4*)(gqh + row * 128 + ck * 16);
            *(uint4*)(sm + 16384 + so) = *(const uint4*)(gql + row * 128 + ck * 16);
        }
    }

    const int kr0 = tid >> 3, kc0 = tid & 7;
    const int kr1 = (tid + 256) >> 3, kc1 = (tid + 256) & 7;
    const uint32_t kso0 = SWZ128(kr0 * 128 + kc0 * 16);
    const uint32_t kso1 = SWZ128(kr1 * 128 + kc1 * 16);

#define ATTN_ISSUE(jt, s) do {                                                  \
    const size_t _tb = hbase + (size_t)((jt) * 64) * DH;                        \
    const char* _kh = (const char*)(kh + _tb);                                  \
    const char* _kl = (const char*)(kl + _tb);                                  \
    const char* _vh = (const char*)(vh + _tb);                                  \
    const char* _vl = (const char*)(vl + _tb);                                  \
    const uint32_t _b = sb + 32768 + (s) * 32768;                               \
    cpa16(_b + kso0,          _kh + kr0 * 128 + kc0 * 16);                      \
    cpa16(_b + kso1,          _kh + kr1 * 128 + kc1 * 16);                      \
    cpa16(_b + 8192 + kso0,   _kl + kr0 * 128 + kc0 * 16);                      \
    cpa16(_b + 8192 + kso1,   _kl + kr1 * 128 + kc1 * 16);                      \
    cpa16(_b + 16384 + kso0,  _vh + kr0 * 128 + kc0 * 16);                      \
    cpa16(_b + 16384 + kso1,  _vh + kr1 * 128 + kc1 * 16);                      \
    cpa16(_b + 24576 + kso0,  _vl + kr0 * 128 + kc0 * 16);                      \
    cpa16(_b + 24576 + kso1,  _vl + kr1 * 128 + kc1 * 16);                      \
    CPA_COMMIT();                                                               \
} while (0)

    float m_run[2] = {-1e30f, -1e30f};
    float l_run[2] = {0.0f, 0.0f};
    float o[8][4] = {};

    const int row_lo = q0 + wid * 16 + (lane >> 2);
    const int njt = 2 * qi + 2;

    ATTN_ISSUE(0, 0);

    for (int jt = 0; jt < njt; jt++) {
        const int kv0 = jt * 64;
        CPA_WAIT0();
        __syncthreads();
        if (jt + 1 < njt) ATTN_ISSUE(jt + 1, (jt + 1) & 1);

        // warps 0-3 (rows q0..q0+63): last kv tile fully masked — skip
        if (wid < 4 && jt == njt - 1) continue;

        const uint32_t uKh = sb + 32768 + (jt & 1) * 32768;
        const uint32_t uKl = uKh + 8192;
        const uint32_t uVh = uKh + 16384;
        const uint32_t uVl = uKh + 24576;

        // ---- S = Qh*Kh + Qh*Kl + Ql*Kh  (m16 x n64, k=64) ----
        float c[8][4] = {};
#pragma unroll
        for (int ks = 0; ks < 4; ks++) {
            uint32_t ah[4], al[4];
            const uint32_t ao = SWZ128(
                (wid * 16 + ((lane >> 3) & 1) * 8 + (lane & 7)) * 128 +
                ks * 32 + (lane >> 4) * 16);
            ldsm4(uQh + ao, ah);
            ldsm4(uQl + ao, al);
#pragma unroll
            for (int np = 0; np < 4; np++) {
                uint32_t bh[4], bl[4];
                const uint32_t bo = SWZ128(
                    (np * 16 + (lane >> 4) * 8 + (lane & 7)) * 128 +
                    ks * 32 + ((lane >> 3) & 1) * 16);
                ldsm4(uKh + bo, bh);
                ldsm4(uKl + bo, bl);
                mma_bf16(c[2 * np + 0], ah, bh + 0);
                mma_bf16(c[2 * np + 0], ah, bl + 0);
                mma_bf16(c[2 * np + 0], al, bh + 0);
                mma_bf16(c[2 * np + 1], ah, bh + 2);
                mma_bf16(c[2 * np + 1], ah, bl + 2);
                mma_bf16(c[2 * np + 1], al, bh + 2);
            }
        }

        // ---- online softmax in registers ----
        float mx[2] = {-1e30f, -1e30f};
#pragma unroll
        for (int nt = 0; nt < 8; nt++) {
#pragma unroll
            for (int j = 0; j < 4; j++) {
                const int half = j >> 1, i = j & 1;
                const int key = kv0 + nt * 8 + (lane & 3) * 2 + i;
                float sv = c[nt][j] * 8.0f;
                if (key > row_lo + 8 * half) sv = -1e30f;
                c[nt][j] = sv;
                mx[half] = fmaxf(mx[half], sv);
            }
        }
#pragma unroll
        for (int half = 0; half < 2; half++) {
            mx[half] = fmaxf(mx[half], __shfl_xor_sync(0xffffffffu, mx[half], 1));
            mx[half] = fmaxf(mx[half], __shfl_xor_sync(0xffffffffu, mx[half], 2));
            float m_new = fmaxf(m_run[half], mx[half]);
            float fac = __expf(m_run[half] - m_new);
            m_run[half] = m_new;
            l_run[half] *= fac;
#pragma unroll
            for (int nt = 0; nt < 8; nt++) {
                o[nt][half * 2 + 0] *= fac;
                o[nt][half * 2 + 1] *= fac;
            }
        }
        float ts[2] = {0.0f, 0.0f};
#pragma unroll
        for (int nt = 0; nt < 8; nt++) {
#pragma unroll
            for (int j = 0; j < 4; j++) {
                float pv = __expf(c[nt][j] - m_run[j >> 1]);
                c[nt][j] = pv;
                ts[j >> 1] += pv;
            }
        }
#pragma unroll
        for (int half = 0; half < 2; half++) {
            ts[half] += __shfl_xor_sync(0xffffffffu, ts[half], 1);
            ts[half] += __shfl_xor_sync(0xffffffffu, ts[half], 2);
            l_run[half] += ts[half];
        }

        // ---- pack P into hi/lo A fragments (registers only) ----
        uint32_t ph[4][4], pl[4][4];
#pragma unroll
        for (int kt = 0; kt < 4; kt++) {
            const float* e = c[2 * kt];
            const float* f = c[2 * kt + 1];
            ph[kt][0] = pack2(e[0], e[1]);
            ph[kt][1] = pack2(e[2], e[3]);
            ph[kt][2] = pack2(f[0], f[1]);
            ph[kt][3] = pack2(f[2], f[3]);
            pl[kt][0] = pack2(e[0] - bfr(e[0]), e[1] - bfr(e[1]));
            pl[kt][1] = pack2(e[2] - bfr(e[2]), e[3] - bfr(e[3]));
            pl[kt][2] = pack2(f[0] - bfr(f[0]), f[1] - bfr(f[1]));
            pl[kt][3] = pack2(f[2] - bfr(f[2]), f[3] - bfr(f[3]));
        }

        // ---- O += Ph*Vh + Ph*Vl + Pl*Vh ----
#pragma unroll
        for (int kt = 0; kt < 4; kt++) {
#pragma unroll
            for (int dp = 0; dp < 4; dp++) {
                uint32_t vhf[4], vlf[4];
                const uint32_t vo = SWZ128(
                    (kt * 16 + (lane & 15)) * 128 +
                    dp * 32 + (lane >> 4) * 16);
                ldsm4t(uVh + vo, vhf);
                ldsm4t(uVl + vo, vlf);
                mma_bf16(o[2 * dp + 0], ph[kt], vhf + 0);
                mma_bf16(o[2 * dp + 0], ph[kt], vlf + 0);
                mma_bf16(o[2 * dp + 0], pl[kt], vhf + 0);
                mma_bf16(o[2 * dp + 1], ph[kt], vhf + 2);
                mma_bf16(o[2 * dp + 1], ph[kt], vlf + 2);
                mma_bf16(o[2 * dp + 1], pl[kt], vhf + 2);
            }
        }
    }

    // ---- epilogue: O /= l, split to bf16 hi/lo, write [tok][1024] ----
    const float inv0 = 1.0f / l_run[0];
    const float inv1 = 1.0f / l_run[1];
    uint32_t* poh = (uint32_t*)oh;
    uint32_t* pol = (uint32_t*)ol;
#pragma unroll
    for (int dt = 0; dt < 8; dt++) {
        const int col = h * DH + dt * 8 + (lane & 3) * 2;
        float a0 = o[dt][0] * inv0, a1 = o[dt][1] * inv0;
        float b0 = o[dt][2] * inv1, b1 = o[dt][3] * inv1;
        const size_t i0 = ((size_t)row_lo * DM + col) >> 1;
        const size_t i1 = ((size_t)(row_lo + 8) * DM + col) >> 1;
        poh[i0] = pack2(a0, a1);
        pol[i0] = pack2(a0 - bfr(a0), a1 - bfr(a1));
        poh[i1] = pack2(b0, b1);
        pol[i1] = pack2(b0 - bfr(b0), b1 - bfr(b1));
    }
}

// ---------------------------------------------------------------------------
extern "C" void kernel_launch(void* const* d_in, const int* in_sizes, int n_in,
                              void* d_out, int out_size)
{
    const float* x  = (const float*)d_in[0];
    const float* Wq = (const float*)d_in[1];
    const float* Wk = (const float*)d_in[2];
    const float* Wv = (const float*)d_in[3];
    const float* Wo = (const float*)d_in[4];
    float* out = (float*)d_out;

    float *q, *k, *v;
    cudaGetSymbolAddress((void**)&q, g_q);
    cudaGetSymbolAddress((void**)&k, g_k);
    cudaGetSymbolAddress((void**)&v, g_v);
    __nv_bfloat16 *xh, *xl, *oh, *ol, *wth, *wtl;
    __nv_bfloat16 *qh, *ql, *kh, *kl, *vh, *vl;
    cudaGetSymbolAddress((void**)&xh, g_xh);
    cudaGetSymbolAddress((void**)&xl, g_xl);
    cudaGetSymbolAddress((void**)&oh, g_oh);
    cudaGetSymbolAddress((void**)&ol, g_ol);
    cudaGetSymbolAddress((void**)&wth, g_wth);
    cudaGetSymbolAddress((void**)&wtl, g_wtl);
    cudaGetSymbolAddress((void**)&qh, g_qh);
    cudaGetSymbolAddress((void**)&ql, g_ql);
    cudaGetSymbolAddress((void**)&kh, g_kh);
    cudaGetSymbolAddress((void**)&kl, g_kl);
    cudaGetSymbolAddress((void**)&vh, g_vh);
    cudaGetSymbolAddress((void**)&vl, g_vl);

    cudaFuncSetAttribute(gemm_mma_kernel<3>,
                         cudaFuncAttributeMaxDynamicSharedMemorySize, GEMM_SMEM);
    cudaFuncSetAttribute(gemm_mma_kernel<1>,
                         cudaFuncAttributeMaxDynamicSharedMemorySize, GEMM_SMEM);
    cudaFuncSetAttribute(attn_mma_kernel,
                         cudaFuncAttributeMaxDynamicSharedMemorySize, ATTN_SMEM);

    const int nvec = N_TOK * DM / 4;

    split_kernel<<<nvec / 256, 256>>>(x, xh, xl);
    tsplit_kernel<<<dim3(32, 32, 4), dim3(32, 8)>>>(Wq, Wk, Wv, Wo, wth, wtl);
    // merged q/k/v projection: z selects weight slice + output
    gemm_mma_kernel<3><<<dim3(DM / 128, N_TOK / 128, 3), 256, GEMM_SMEM>>>(
        xh, xl, wth, wtl, q, k, v);
    qkv_prep_kernel<<<3 * N_TOK * NHEADS / 8, 256>>>(q, k, v, qh, ql, kh, kl, vh, vl);
    attn_mma_kernel<<<dim3(N_TOK / 128, NHEADS), 256, ATTN_SMEM>>>(qh, ql, kh, kl, vh, vl, oh, ol);
    gemm_mma_kernel<1><<<dim3(DM / 128, N_TOK / 128, 1), 256, GEMM_SMEM>>>(
        oh, ol, wth + 3 * (size_t)DM * DM, wtl + 3 * (size_t)DM * DM, out, nullptr, nullptr);
}

// round 11
// speedup vs baseline: 1.0103x; 1.0103x over previous
#include <cuda_runtime.h>
#include <cuda_bf16.h>
#include <cstdint>
#include <math.h>

#define N_TOK 4096
#define DM 1024
#define NHEADS 16
#define DH 64

// ---------------------------------------------------------------------------
// Scratch (allocation-free rule: __device__ globals)
// ---------------------------------------------------------------------------
__device__ float g_q[N_TOK * DM];
__device__ float g_k[N_TOK * DM];
__device__ float g_v[N_TOK * DM];

__device__ __nv_bfloat16 g_xh[N_TOK * DM];
__device__ __nv_bfloat16 g_xl[N_TOK * DM];
__device__ __nv_bfloat16 g_oh[N_TOK * DM];
__device__ __nv_bfloat16 g_ol[N_TOK * DM];
__device__ __nv_bfloat16 g_wth[4 * DM * DM];  // W^T hi: [w][n][k]
__device__ __nv_bfloat16 g_wtl[4 * DM * DM];  // W^T lo
// normalized/split attention operands, [head][tok][64]
__device__ __nv_bfloat16 g_qh[N_TOK * DM];
__device__ __nv_bfloat16 g_ql[N_TOK * DM];
__device__ __nv_bfloat16 g_kh[N_TOK * DM];
__device__ __nv_bfloat16 g_kl[N_TOK * DM];
__device__ __nv_bfloat16 g_vh[N_TOK * DM];
__device__ __nv_bfloat16 g_vl[N_TOK * DM];

#define SWZ64(o)  ((o) ^ (((o) >> 3) & 0x30))
#define SWZ128(o) ((o) ^ (((o) >> 3) & 0x70))

__device__ __forceinline__ uint32_t smem_u32(const void* p) {
    uint32_t a;
    asm("{ .reg .u64 t; cvta.to.shared.u64 t, %1; cvt.u32.u64 %0, t; }"
        : "=r"(a) : "l"(p));
    return a;
}
__device__ __forceinline__ void cpa16(uint32_t dst, const void* src) {
    asm volatile("cp.async.cg.shared.global [%0], [%1], 16;"
                 :: "r"(dst), "l"(src));
}
#define CPA_COMMIT() asm volatile("cp.async.commit_group;" ::: "memory")
#define CPA_WAIT0()  asm volatile("cp.async.wait_group 0;" ::: "memory")

__device__ __forceinline__ void ldsm4(uint32_t addr, uint32_t r[4]) {
    asm volatile("ldmatrix.sync.aligned.m8n8.x4.shared.b16 {%0,%1,%2,%3}, [%4];"
                 : "=r"(r[0]), "=r"(r[1]), "=r"(r[2]), "=r"(r[3]) : "r"(addr));
}
__device__ __forceinline__ void ldsm4t(uint32_t addr, uint32_t r[4]) {
    asm volatile("ldmatrix.sync.aligned.m8n8.x4.trans.shared.b16 {%0,%1,%2,%3}, [%4];"
                 : "=r"(r[0]), "=r"(r[1]), "=r"(r[2]), "=r"(r[3]) : "r"(addr));
}
__device__ __forceinline__ void ldsm2(uint32_t addr, uint32_t r[2]) {
    asm volatile("ldmatrix.sync.aligned.m8n8.x2.shared.b16 {%0,%1}, [%2];"
                 : "=r"(r[0]), "=r"(r[1]) : "r"(addr));
}
__device__ __forceinline__ void mma_bf16(float c[4], const uint32_t a[4],
                                         const uint32_t b[2]) {
    asm volatile(
        "mma.sync.aligned.m16n8k16.row.col.f32.bf16.bf16.f32 "
        "{%0,%1,%2,%3}, {%4,%5,%6,%7}, {%8,%9}, {%0,%1,%2,%3};"
        : "+f"(c[0]), "+f"(c[1]), "+f"(c[2]), "+f"(c[3])
        : "r"(a[0]), "r"(a[1]), "r"(a[2]), "r"(a[3]), "r"(b[0]), "r"(b[1]));
}
__device__ __forceinline__ uint32_t pack2(float a, float b) {
    uint32_t r;
    asm("cvt.rn.bf16x2.f32 %0, %1, %2;" : "=r"(r) : "f"(b), "f"(a));
    return r;
}
__device__ __forceinline__ float bfr(float x) {
    return __bfloat162float(__float2bfloat16(x));
}

// ---------------------------------------------------------------------------
// Split fp32 -> (hi, lo) bf16, elementwise (for x).
// ---------------------------------------------------------------------------
__global__ __launch_bounds__(256) void split_kernel(
    const float* __restrict__ src, __nv_bfloat16* __restrict__ h,
    __nv_bfloat16* __restrict__ l)
{
    int i = blockIdx.x * 256 + threadIdx.x;
    float4 v = ((const float4*)src)[i];
    ((uint32_t*)h)[2 * i + 0] = pack2(v.x, v.y);
    ((uint32_t*)h)[2 * i + 1] = pack2(v.z, v.w);
    ((uint32_t*)l)[2 * i + 0] = pack2(v.x - bfr(v.x), v.y - bfr(v.y));
    ((uint32_t*)l)[2 * i + 1] = pack2(v.z - bfr(v.z), v.w - bfr(v.w));
}

// ---------------------------------------------------------------------------
// Transpose + split all 4 weight matrices: out[w][n][k] = split(W_w[k][n]).
// ---------------------------------------------------------------------------
__global__ __launch_bounds__(256) void tsplit_kernel(
    const float* __restrict__ W0, const float* __restrict__ W1,
    const float* __restrict__ W2, const float* __restrict__ W3,
    __nv_bfloat16* __restrict__ H, __nv_bfloat16* __restrict__ L)
{
    const float* W = (blockIdx.z == 0) ? W0 : (blockIdx.z == 1) ? W1
                   : (blockIdx.z == 2) ? W2 : W3;
    __nv_bfloat16* h = H + (size_t)blockIdx.z * DM * DM;
    __nv_bfloat16* l = L + (size_t)blockIdx.z * DM * DM;
    __shared__ float t[32][33];
    const int bx = blockIdx.x * 32;
    const int by = blockIdx.y * 32;
    const int tx = threadIdx.x;
    for (int j = threadIdx.y; j < 32; j += 8)
        t[j][tx] = W[(size_t)(by + j) * DM + bx + tx];
    __syncthreads();
    for (int j = threadIdx.y; j < 32; j += 8) {
        float v = t[tx][j];
        __nv_bfloat16 hv = __float2bfloat16(v);
        __nv_bfloat16 lv = __float2bfloat16(v - __bfloat162float(hv));
        size_t idx = (size_t)(bx + j) * DM + by + tx;
        h[idx] = hv;
        l[idx] = lv;
    }
}

// ---------------------------------------------------------------------------
// Prep: q,k (l2norm) and v -> hi/lo bf16 in [head][tok][64] layout.
// ---------------------------------------------------------------------------
__global__ __launch_bounds__(256) void qkv_prep_kernel(
    const float* __restrict__ q, const float* __restrict__ k,
    const float* __restrict__ v,
    __nv_bfloat16* __restrict__ qh, __nv_bfloat16* __restrict__ ql,
    __nv_bfloat16* __restrict__ kh, __nv_bfloat16* __restrict__ kl,
    __nv_bfloat16* __restrict__ vh, __nv_bfloat16* __restrict__ vl)
{
    const int gwarp = blockIdx.x * 8 + (threadIdx.x >> 5);
    const int lane = threadIdx.x & 31;
    const int buf = gwarp >> 16;           // 0=q, 1=k, 2=v
    const int rem = gwarp & 0xFFFF;
    const int head = rem & 15, tok = rem >> 4;

    const float* src = (buf == 0) ? q : (buf == 1) ? k : v;
    __nv_bfloat16* dh = (buf == 0) ? qh : (buf == 1) ? kh : vh;
    __nv_bfloat16* dl = (buf == 0) ? ql : (buf == 1) ? kl : vl;

    float2 val = *(const float2*)&src[(size_t)tok * DM + head * DH + lane * 2];
    if (buf < 2) {
        float ss = val.x * val.x + val.y * val.y;
#pragma unroll
        for (int off = 16; off > 0; off >>= 1)
            ss += __shfl_xor_sync(0xffffffffu, ss, off);
        float inv = 1.0f / fmaxf(sqrtf(ss), 1e-12f);
        val.x *= inv;
        val.y *= inv;
    }
    const size_t di = ((size_t)head * N_TOK + tok) * DH + lane * 2;
    ((uint32_t*)dh)[di >> 1] = pack2(val.x, val.y);
    ((uint32_t*)dl)[di >> 1] = pack2(val.x - bfr(val.x), val.y - bfr(val.y));
}

// ---------------------------------------------------------------------------
// HMMA split-bf16 GEMM with cp.async double buffering.
// C[M x 1024] = A @ B^T. CTA 128x128, BK=32, 8 warps (2m x 4n).
// NOUT == 3: blockIdx.z selects weight slice + output (merged q/k/v).
// ---------------------------------------------------------------------------
#define GEMM_SMEM (2 * 32768)

template <int NOUT>
__global__ __launch_bounds__(256, 2) void gemm_mma_kernel(
    const __nv_bfloat16* __restrict__ Ah, const __nv_bfloat16* __restrict__ Al,
    const __nv_bfloat16* __restrict__ Bh_, const __nv_bfloat16* __restrict__ Bl_,
    float* __restrict__ C0, float* __restrict__ C1, float* __restrict__ C2)
{
    extern __shared__ char sm[];
    const uint32_t sbase = smem_u32(sm);

    const int tid = threadIdx.x;
    const int wid = tid >> 5, lane = tid & 31;
    const int wm = wid & 1, wn = wid >> 1;
    const int m0 = blockIdx.y * 128, n0 = blockIdx.x * 128;

    const __nv_bfloat16* Bh = Bh_;
    const __nv_bfloat16* Bl = Bl_;
    float* C = C0;
    if (NOUT == 3) {
        const size_t woff = (size_t)blockIdx.z * DM * DM;
        Bh = Bh_ + woff;
        Bl = Bl_ + woff;
        C = (blockIdx.z == 0) ? C0 : (blockIdx.z == 1) ? C1 : C2;
    }

    const int a_row = ((lane >> 3) & 1) * 8 + (lane & 7);
    const int a_kb  = (lane >> 4) * 16;
    const int l15 = lane & 15;
    const int b_row = l15 & 7;
    const int b_kb  = (l15 >> 3) * 16;

    const int r_0 = tid >> 2, kb_0 = tid & 3;
    const int r_1 = (tid + 256) >> 2, kb_1 = (tid + 256) & 3;
    const uint32_t so_0 = SWZ64(r_0 * 64 + kb_0 * 16);
    const uint32_t so_1 = SWZ64(r_1 * 64 + kb_1 * 16);

    float c[4][4][4] = {};

#define GEMM_ISSUE(kc, s) do {                                                  \
    const int _k0 = (kc) * 32;                                                  \
    const uint32_t _b = sbase + (s) * 32768;                                    \
    const size_t _ga0 = (size_t)(m0 + r_0) * DM + _k0 + kb_0 * 8;               \
    const size_t _ga1 = (size_t)(m0 + r_1) * DM + _k0 + kb_1 * 8;               \
    const size_t _gb0 = (size_t)(n0 + r_0) * DM + _k0 + kb_0 * 8;               \
    const size_t _gb1 = (size_t)(n0 + r_1) * DM + _k0 + kb_1 * 8;               \
    cpa16(_b + so_0,             Ah + _ga0);                                    \
    cpa16(_b + so_1,             Ah + _ga1);                                    \
    cpa16(_b + 8192  + so_0,     Al + _ga0);                                    \
    cpa16(_b + 8192  + so_1,     Al + _ga1);                                    \
    cpa16(_b + 16384 + so_0,     Bh + _gb0);                                    \
    cpa16(_b + 16384 + so_1,     Bh + _gb1);                                    \
    cpa16(_b + 24576 + so_0,     Bl + _gb0);                                    \
    cpa16(_b + 24576 + so_1,     Bl + _gb1);                                    \
    CPA_COMMIT();                                                               \
} while (0)

    GEMM_ISSUE(0, 0);

    for (int kc = 0; kc < 32; kc++) {
        CPA_WAIT0();
        __syncthreads();
        if (kc < 31) GEMM_ISSUE(kc + 1, (kc + 1) & 1);

        const uint32_t uAh = sbase + (kc & 1) * 32768;
        const uint32_t uAl = uAh + 8192;
        const uint32_t uBh = uAh + 16384;
        const uint32_t uBl = uAh + 24576;

#pragma unroll
        for (int ks = 0; ks < 2; ks++) {
            uint32_t bh[4][2], bl[4][2];
#pragma unroll
            for (int nt = 0; nt < 4; nt++) {
                const uint32_t bo =
                    SWZ64((wn * 32 + nt * 8 + b_row) * 64 + ks * 32 + b_kb);
                ldsm2(uBh + bo, bh[nt]);
                ldsm2(uBl + bo, bl[nt]);
            }
#pragma unroll
            for (int mt = 0; mt < 4; mt++) {
                uint32_t ah[4], al[4];
                const uint32_t ao =
                    SWZ64((wm * 64 + mt * 16 + a_row) * 64 + ks * 32 + a_kb);
                ldsm4(uAh + ao, ah);
                ldsm4(uAl + ao, al);
#pragma unroll
                for (int nt = 0; nt < 4; nt++) {
                    mma_bf16(c[mt][nt], ah, bh[nt]);
                    mma_bf16(c[mt][nt], ah, bl[nt]);
                    mma_bf16(c[mt][nt], al, bh[nt]);
                }
            }
        }
        __syncthreads();
    }

    const int gq = lane >> 2, tq = lane & 3;
#pragma unroll
    for (int mt = 0; mt < 4; mt++) {
#pragma unroll
        for (int nt = 0; nt < 4; nt++) {
            const int row = m0 + wm * 64 + mt * 16 + gq;
            const int col = n0 + wn * 32 + nt * 8 + tq * 2;
            *(float2*)&C[(size_t)row * DM + col] =
                make_float2(c[mt][nt][0], c[mt][nt][1]);
            *(float2*)&C[(size_t)(row + 8) * DM + col] =
                make_float2(c[mt][nt][2], c[mt][nt][3]);
        }
    }
}

// ---------------------------------------------------------------------------
// Tensor-core causal flash attention, 2 CTAs/SM, register-budgeted:
// P pack and PV are interleaved per k-step so peak live regs fit the
// 128-reg cap that __launch_bounds__(256,2) imposes (no spills).
// ---------------------------------------------------------------------------
#define ATTN_SMEM (32768 + 2 * 32768)

__global__ __launch_bounds__(256, 2) void attn_mma_kernel(
    const __nv_bfloat16* __restrict__ qh, const __nv_bfloat16* __restrict__ ql,
    const __nv_bfloat16* __restrict__ kh, const __nv_bfloat16* __restrict__ kl,
    const __nv_bfloat16* __restrict__ vh, const __nv_bfloat16* __restrict__ vl,
    __nv_bfloat16* __restrict__ oh, __nv_bfloat16* __restrict__ ol)
{
    extern __shared__ char sm[];
    const uint32_t sb = smem_u32(sm);
    const uint32_t uQh = sb, uQl = sb + 16384;

    const int tid = threadIdx.x, wid = tid >> 5, lane = tid & 31;
    const int h = blockIdx.y;
    const int qi = gridDim.x - 1 - blockIdx.x;
    const int q0 = qi * 128;
    const size_t hbase = (size_t)h * N_TOK * DH;  // bf16 elems

    // ---- load Q hi/lo tiles (each 128 rows x 128B), swizzled ----
    {
        const char* gqh = (const char*)(qh + hbase + (size_t)q0 * DH);
        const char* gql = (const char*)(ql + hbase + (size_t)q0 * DH);
#pragma unroll
        for (int it = 0; it < 4; it++) {
            int idx = tid + 256 * it;
            int row = idx >> 3, ck = idx & 7;
            uint32_t so = SWZ128(row * 128 + ck * 16);
            *(uint4*)(sm + so) = *(const uint4*)(gqh + row * 128 + ck * 16);
            *(uint4*)(sm + 16384 + so) = *(const uint4*)(gql + row * 128 + ck * 16);
        }
    }

    const int kr0 = tid >> 3, kc0 = tid & 7;
    const int kr1 = (tid + 256) >> 3, kc1 = (tid + 256) & 7;
    const uint32_t kso0 = SWZ128(kr0 * 128 + kc0 * 16);
    const uint32_t kso1 = SWZ128(kr1 * 128 + kc1 * 16);

#define ATTN_ISSUE(jt, s) do {                                                  \
    const size_t _tb = hbase + (size_t)((jt) * 64) * DH;                        \
    const char* _kh = (const char*)(kh + _tb);                                  \
    const char* _kl = (const char*)(kl + _tb);                                  \
    const char* _vh = (const char*)(vh + _tb);                                  \
    const char* _vl = (const char*)(vl + _tb);                                  \
    const uint32_t _b = sb + 32768 + (s) * 32768;                               \
    cpa16(_b + kso0,          _kh + kr0 * 128 + kc0 * 16);                      \
    cpa16(_b + kso1,          _kh + kr1 * 128 + kc1 * 16);                      \
    cpa16(_b + 8192 + kso0,   _kl + kr0 * 128 + kc0 * 16);                      \
    cpa16(_b + 8192 + kso1,   _kl + kr1 * 128 + kc1 * 16);                      \
    cpa16(_b + 16384 + kso0,  _vh + kr0 * 128 + kc0 * 16);                      \
    cpa16(_b + 16384 + kso1,  _vh + kr1 * 128 + kc1 * 16);                      \
    cpa16(_b + 24576 + kso0,  _vl + kr0 * 128 + kc0 * 16);                      \
    cpa16(_b + 24576 + kso1,  _vl + kr1 * 128 + kc1 * 16);                      \
    CPA_COMMIT();                                                               \
} while (0)

    float m_run[2] = {-1e30f, -1e30f};
    float l_run[2] = {0.0f, 0.0f};
    float o[8][4] = {};

    const int row_lo = q0 + wid * 16 + (lane >> 2);
    const int njt = 2 * qi + 2;

    ATTN_ISSUE(0, 0);

    for (int jt = 0; jt < njt; jt++) {
        const int kv0 = jt * 64;
        CPA_WAIT0();
        __syncthreads();
        if (jt + 1 < njt) ATTN_ISSUE(jt + 1, (jt + 1) & 1);

        // warps 0-3 (rows q0..q0+63): last kv tile fully masked — skip
        if (wid < 4 && jt == njt - 1) continue;

        const uint32_t uKh = sb + 32768 + (jt & 1) * 32768;
        const uint32_t uKl = uKh + 8192;
        const uint32_t uVh = uKh + 16384;
        const uint32_t uVl = uKh + 24576;

        // ---- S = Qh*Kh + Qh*Kl + Ql*Kh  (m16 x n64, k=64) ----
        float c[8][4] = {};
#pragma unroll
        for (int ks = 0; ks < 4; ks++) {
            uint32_t ah[4], al[4];
            const uint32_t ao = SWZ128(
                (wid * 16 + ((lane >> 3) & 1) * 8 + (lane & 7)) * 128 +
                ks * 32 + (lane >> 4) * 16);
            ldsm4(uQh + ao, ah);
            ldsm4(uQl + ao, al);
#pragma unroll
            for (int np = 0; np < 4; np++) {
                uint32_t bh[4], bl[4];
                const uint32_t bo = SWZ128(
                    (np * 16 + (lane >> 4) * 8 + (lane & 7)) * 128 +
                    ks * 32 + ((lane >> 3) & 1) * 16);
                ldsm4(uKh + bo, bh);
                ldsm4(uKl + bo, bl);
                mma_bf16(c[2 * np + 0], ah, bh + 0);
                mma_bf16(c[2 * np + 0], ah, bl + 0);
                mma_bf16(c[2 * np + 0], al, bh + 0);
                mma_bf16(c[2 * np + 1], ah, bh + 2);
                mma_bf16(c[2 * np + 1], ah, bl + 2);
                mma_bf16(c[2 * np + 1], al, bh + 2);
            }
        }

        // ---- online softmax in registers ----
        float mx[2] = {-1e30f, -1e30f};
#pragma unroll
        for (int nt = 0; nt < 8; nt++) {
#pragma unroll
            for (int j = 0; j < 4; j++) {
                const int half = j >> 1, i = j & 1;
                const int key = kv0 + nt * 8 + (lane & 3) * 2 + i;
                float sv = c[nt][j] * 8.0f;
                if (key > row_lo + 8 * half) sv = -1e30f;
                c[nt][j] = sv;
                mx[half] = fmaxf(mx[half], sv);
            }
        }
#pragma unroll
        for (int half = 0; half < 2; half++) {
            mx[half] = fmaxf(mx[half], __shfl_xor_sync(0xffffffffu, mx[half], 1));
            mx[half] = fmaxf(mx[half], __shfl_xor_sync(0xffffffffu, mx[half], 2));
            float m_new = fmaxf(m_run[half], mx[half]);
            float fac = __expf(m_run[half] - m_new);
            m_run[half] = m_new;
            l_run[half] *= fac;
#pragma unroll
            for (int nt = 0; nt < 8; nt++) {
                o[nt][half * 2 + 0] *= fac;
                o[nt][half * 2 + 1] *= fac;
            }
        }
        float ts[2] = {0.0f, 0.0f};
#pragma unroll
        for (int nt = 0; nt < 8; nt++) {
#pragma unroll
            for (int j = 0; j < 4; j++) {
                float pv = __expf(c[nt][j] - m_run[j >> 1]);
                c[nt][j] = pv;
                ts[j >> 1] += pv;
            }
        }
#pragma unroll
        for (int half = 0; half < 2; half++) {
            ts[half] += __shfl_xor_sync(0xffffffffu, ts[half], 1);
            ts[half] += __shfl_xor_sync(0xffffffffu, ts[half], 2);
            l_run[half] += ts[half];
        }

        // ---- PV interleaved with pack (short ph/pl live range: 8 regs) ----
#pragma unroll
        for (int kt = 0; kt < 4; kt++) {
            uint32_t ph[4], pl[4];
            {
                const float* e = c[2 * kt];
                const float* f = c[2 * kt + 1];
                ph[0] = pack2(e[0], e[1]);
                ph[1] = pack2(e[2], e[3]);
                ph[2] = pack2(f[0], f[1]);
                ph[3] = pack2(f[2], f[3]);
                pl[0] = pack2(e[0] - bfr(e[0]), e[1] - bfr(e[1]));
                pl[1] = pack2(e[2] - bfr(e[2]), e[3] - bfr(e[3]));
                pl[2] = pack2(f[0] - bfr(f[0]), f[1] - bfr(f[1]));
                pl[3] = pack2(f[2] - bfr(f[2]), f[3] - bfr(f[3]));
            }
#pragma unroll
            for (int dp = 0; dp < 4; dp++) {
                uint32_t vhf[4], vlf[4];
                const uint32_t vo = SWZ128(
                    (kt * 16 + (lane & 15)) * 128 +
                    dp * 32 + (lane >> 4) * 16);
                ldsm4t(uVh + vo, vhf);
                ldsm4t(uVl + vo, vlf);
                mma_bf16(o[2 * dp + 0], ph, vhf + 0);
                mma_bf16(o[2 * dp + 0], ph, vlf + 0);
                mma_bf16(o[2 * dp + 0], pl, vhf + 0);
                mma_bf16(o[2 * dp + 1], ph, vhf + 2);
                mma_bf16(o[2 * dp + 1], ph, vlf + 2);
                mma_bf16(o[2 * dp + 1], pl, vhf + 2);
            }
        }
    }

    // ---- epilogue: O /= l, split to bf16 hi/lo, write [tok][1024] ----
    const float inv0 = 1.0f / l_run[0];
    const float inv1 = 1.0f / l_run[1];
    uint32_t* poh = (uint32_t*)oh;
    uint32_t* pol = (uint32_t*)ol;
#pragma unroll
    for (int dt = 0; dt < 8; dt++) {
        const int col = h * DH + dt * 8 + (lane & 3) * 2;
        float a0 = o[dt][0] * inv0, a1 = o[dt][1] * inv0;
        float b0 = o[dt][2] * inv1, b1 = o[dt][3] * inv1;
        const size_t i0 = ((size_t)row_lo * DM + col) >> 1;
        const size_t i1 = ((size_t)(row_lo + 8) * DM + col) >> 1;
        poh[i0] = pack2(a0, a1);
        pol[i0] = pack2(a0 - bfr(a0), a1 - bfr(a1));
        poh[i1] = pack2(b0, b1);
        pol[i1] = pack2(b0 - bfr(b0), b1 - bfr(b1));
    }
}

// ---------------------------------------------------------------------------
extern "C" void kernel_launch(void* const* d_in, const int* in_sizes, int n_in,
                              void* d_out, int out_size)
{
    const float* x  = (const float*)d_in[0];
    const float* Wq = (const float*)d_in[1];
    const float* Wk = (const float*)d_in[2];
    const float* Wv = (const float*)d_in[3];
    const float* Wo = (const float*)d_in[4];
    float* out = (float*)d_out;

    float *q, *k, *v;
    cudaGetSymbolAddress((void**)&q, g_q);
    cudaGetSymbolAddress((void**)&k, g_k);
    cudaGetSymbolAddress((void**)&v, g_v);
    __nv_bfloat16 *xh, *xl, *oh, *ol, *wth, *wtl;
    __nv_bfloat16 *qh, *ql, *kh, *kl, *vh, *vl;
    cudaGetSymbolAddress((void**)&xh, g_xh);
    cudaGetSymbolAddress((void**)&xl, g_xl);
    cudaGetSymbolAddress((void**)&oh, g_oh);
    cudaGetSymbolAddress((void**)&ol, g_ol);
    cudaGetSymbolAddress((void**)&wth, g_wth);
    cudaGetSymbolAddress((void**)&wtl, g_wtl);
    cudaGetSymbolAddress((void**)&qh, g_qh);
    cudaGetSymbolAddress((void**)&ql, g_ql);
    cudaGetSymbolAddress((void**)&kh, g_kh);
    cudaGetSymbolAddress((void**)&kl, g_kl);
    cudaGetSymbolAddress((void**)&vh, g_vh);
    cudaGetSymbolAddress((void**)&vl, g_vl);

    cudaFuncSetAttribute(gemm_mma_kernel<3>,
                         cudaFuncAttributeMaxDynamicSharedMemorySize, GEMM_SMEM);
    cudaFuncSetAttribute(gemm_mma_kernel<1>,
                         cudaFuncAttributeMaxDynamicSharedMemorySize, GEMM_SMEM);
    cudaFuncSetAttribute(attn_mma_kernel,
                         cudaFuncAttributeMaxDynamicSharedMemorySize, ATTN_SMEM);

    const int nvec = N_TOK * DM / 4;

    split_kernel<<<nvec / 256, 256>>>(x, xh, xl);
    tsplit_kernel<<<dim3(32, 32, 4), dim3(32, 8)>>>(Wq, Wk, Wv, Wo, wth, wtl);
    gemm_mma_kernel<3><<<dim3(DM / 128, N_TOK / 128, 3), 256, GEMM_SMEM>>>(
        xh, xl, wth, wtl, q, k, v);
    qkv_prep_kernel<<<3 * N_TOK * NHEADS / 8, 256>>>(q, k, v, qh, ql, kh, kl, vh, vl);
    attn_mma_kernel<<<dim3(N_TOK / 128, NHEADS), 256, ATTN_SMEM>>>(qh, ql, kh, kl, vh, vl, oh, ol);
    gemm_mma_kernel<1><<<dim3(DM / 128, N_TOK / 128, 1), 256, GEMM_SMEM>>>(
        oh, ol, wth + 3 * (size_t)DM * DM, wtl + 3 * (size_t)DM * DM, out, nullptr, nullptr);
}

// round 12
// speedup vs baseline: 1.0863x; 1.0752x over previous
#include <cuda_runtime.h>
#include <cuda_bf16.h>
#include <cstdint>
#include <math.h>

#define N_TOK 4096
#define DM 1024
#define NHEADS 16
#define DH 64

// ---------------------------------------------------------------------------
// Scratch (allocation-free rule: __device__ globals)
// ---------------------------------------------------------------------------
__device__ float g_q[N_TOK * DM];
__device__ float g_k[N_TOK * DM];
__device__ float g_v[N_TOK * DM];

__device__ __nv_bfloat16 g_xh[N_TOK * DM];
__device__ __nv_bfloat16 g_xl[N_TOK * DM];
__device__ __nv_bfloat16 g_oh[N_TOK * DM];
__device__ __nv_bfloat16 g_ol[N_TOK * DM];
__device__ __nv_bfloat16 g_wth[4 * DM * DM];  // W^T hi: [w][n][k]
__device__ __nv_bfloat16 g_wtl[4 * DM * DM];  // W^T lo
// normalized/split attention operands, [head][tok][64]
__device__ __nv_bfloat16 g_qh[N_TOK * DM];
__device__ __nv_bfloat16 g_ql[N_TOK * DM];
__device__ __nv_bfloat16 g_kh[N_TOK * DM];
__device__ __nv_bfloat16 g_kl[N_TOK * DM];
__device__ __nv_bfloat16 g_vh[N_TOK * DM];
__device__ __nv_bfloat16 g_vl[N_TOK * DM];

#define SWZ64(o)  ((o) ^ (((o) >> 3) & 0x30))
#define SWZ128(o) ((o) ^ (((o) >> 3) & 0x70))

__device__ __forceinline__ uint32_t smem_u32(const void* p) {
    uint32_t a;
    asm("{ .reg .u64 t; cvta.to.shared.u64 t, %1; cvt.u32.u64 %0, t; }"
        : "=r"(a) : "l"(p));
    return a;
}
__device__ __forceinline__ void cpa16(uint32_t dst, const void* src) {
    asm volatile("cp.async.cg.shared.global [%0], [%1], 16;"
                 :: "r"(dst), "l"(src));
}
#define CPA_COMMIT() asm volatile("cp.async.commit_group;" ::: "memory")
#define CPA_WAIT0()  asm volatile("cp.async.wait_group 0;" ::: "memory")

__device__ __forceinline__ void ldsm4(uint32_t addr, uint32_t r[4]) {
    asm volatile("ldmatrix.sync.aligned.m8n8.x4.shared.b16 {%0,%1,%2,%3}, [%4];"
                 : "=r"(r[0]), "=r"(r[1]), "=r"(r[2]), "=r"(r[3]) : "r"(addr));
}
__device__ __forceinline__ void ldsm4t(uint32_t addr, uint32_t r[4]) {
    asm volatile("ldmatrix.sync.aligned.m8n8.x4.trans.shared.b16 {%0,%1,%2,%3}, [%4];"
                 : "=r"(r[0]), "=r"(r[1]), "=r"(r[2]), "=r"(r[3]) : "r"(addr));
}
__device__ __forceinline__ void ldsm2(uint32_t addr, uint32_t r[2]) {
    asm volatile("ldmatrix.sync.aligned.m8n8.x2.shared.b16 {%0,%1}, [%2];"
                 : "=r"(r[0]), "=r"(r[1]) : "r"(addr));
}
__device__ __forceinline__ void mma_bf16(float c[4], const uint32_t a[4],
                                         const uint32_t b[2]) {
    asm volatile(
        "mma.sync.aligned.m16n8k16.row.col.f32.bf16.bf16.f32 "
        "{%0,%1,%2,%3}, {%4,%5,%6,%7}, {%8,%9}, {%0,%1,%2,%3};"
        : "+f"(c[0]), "+f"(c[1]), "+f"(c[2]), "+f"(c[3])
        : "r"(a[0]), "r"(a[1]), "r"(a[2]), "r"(a[3]), "r"(b[0]), "r"(b[1]));
}
__device__ __forceinline__ uint32_t pack2(float a, float b) {
    uint32_t r;
    asm("cvt.rn.bf16x2.f32 %0, %1, %2;" : "=r"(r) : "f"(b), "f"(a));
    return r;
}
__device__ __forceinline__ float bfr(float x) {
    return __bfloat162float(__float2bfloat16(x));
}

// ---------------------------------------------------------------------------
// Split fp32 -> (hi, lo) bf16, elementwise (for x).
// ---------------------------------------------------------------------------
__global__ __launch_bounds__(256) void split_kernel(
    const float* __restrict__ src, __nv_bfloat16* __restrict__ h,
    __nv_bfloat16* __restrict__ l)
{
    int i = blockIdx.x * 256 + threadIdx.x;
    float4 v = ((const float4*)src)[i];
    ((uint32_t*)h)[2 * i + 0] = pack2(v.x, v.y);
    ((uint32_t*)h)[2 * i + 1] = pack2(v.z, v.w);
    ((uint32_t*)l)[2 * i + 0] = pack2(v.x - bfr(v.x), v.y - bfr(v.y));
    ((uint32_t*)l)[2 * i + 1] = pack2(v.z - bfr(v.z), v.w - bfr(v.w));
}

// ---------------------------------------------------------------------------
// Transpose + split all 4 weight matrices: out[w][n][k] = split(W_w[k][n]).
// ---------------------------------------------------------------------------
__global__ __launch_bounds__(256) void tsplit_kernel(
    const float* __restrict__ W0, const float* __restrict__ W1,
    const float* __restrict__ W2, const float* __restrict__ W3,
    __nv_bfloat16* __restrict__ H, __nv_bfloat16* __restrict__ L)
{
    const float* W = (blockIdx.z == 0) ? W0 : (blockIdx.z == 1) ? W1
                   : (blockIdx.z == 2) ? W2 : W3;
    __nv_bfloat16* h = H + (size_t)blockIdx.z * DM * DM;
    __nv_bfloat16* l = L + (size_t)blockIdx.z * DM * DM;
    __shared__ float t[32][33];
    const int bx = blockIdx.x * 32;
    const int by = blockIdx.y * 32;
    const int tx = threadIdx.x;
    for (int j = threadIdx.y; j < 32; j += 8)
        t[j][tx] = W[(size_t)(by + j) * DM + bx + tx];
    __syncthreads();
    for (int j = threadIdx.y; j < 32; j += 8) {
        float v = t[tx][j];
        __nv_bfloat16 hv = __float2bfloat16(v);
        __nv_bfloat16 lv = __float2bfloat16(v - __bfloat162float(hv));
        size_t idx = (size_t)(bx + j) * DM + by + tx;
        h[idx] = hv;
        l[idx] = lv;
    }
}

// ---------------------------------------------------------------------------
// Prep: one warp per (tok, head) handles q (norm), k (norm), v (copy),
// all split into hi/lo bf16 in [head][tok][64] layout.
// ---------------------------------------------------------------------------
__global__ __launch_bounds__(256) void qkv_prep_kernel(
    const float* __restrict__ q, const float* __restrict__ k,
    const float* __restrict__ v,
    __nv_bfloat16* __restrict__ qh, __nv_bfloat16* __restrict__ ql,
    __nv_bfloat16* __restrict__ kh, __nv_bfloat16* __restrict__ kl,
    __nv_bfloat16* __restrict__ vh, __nv_bfloat16* __restrict__ vl)
{
    const int gwarp = blockIdx.x * 8 + (threadIdx.x >> 5);  // tok*16 + head
    const int lane = threadIdx.x & 31;
    const int head = gwarp & 15, tok = gwarp >> 4;

    const size_t si = (size_t)tok * DM + head * DH + lane * 2;
    const size_t di = (((size_t)head * N_TOK + tok) * DH + lane * 2) >> 1;

    float2 qv = *(const float2*)&q[si];
    float2 kv = *(const float2*)&k[si];
    float2 vv = *(const float2*)&v[si];

    float sq = qv.x * qv.x + qv.y * qv.y;
    float sk = kv.x * kv.x + kv.y * kv.y;
#pragma unroll
    for (int off = 16; off > 0; off >>= 1) {
        sq += __shfl_xor_sync(0xffffffffu, sq, off);
        sk += __shfl_xor_sync(0xffffffffu, sk, off);
    }
    float iq = 1.0f / fmaxf(sqrtf(sq), 1e-12f);
    float ik = 1.0f / fmaxf(sqrtf(sk), 1e-12f);
    qv.x *= iq; qv.y *= iq;
    kv.x *= ik; kv.y *= ik;

    ((uint32_t*)qh)[di] = pack2(qv.x, qv.y);
    ((uint32_t*)ql)[di] = pack2(qv.x - bfr(qv.x), qv.y - bfr(qv.y));
    ((uint32_t*)kh)[di] = pack2(kv.x, kv.y);
    ((uint32_t*)kl)[di] = pack2(kv.x - bfr(kv.x), kv.y - bfr(kv.y));
    ((uint32_t*)vh)[di] = pack2(vv.x, vv.y);
    ((uint32_t*)vl)[di] = pack2(vv.x - bfr(vv.x), vv.y - bfr(vv.y));
}

// ---------------------------------------------------------------------------
// HMMA split-bf16 GEMM with cp.async double buffering.
// C[M x 1024] = A @ B^T. CTA 128x128, BK=32, 8 warps (2m x 4n).
// NOUT == 3: blockIdx.z selects weight slice + output (merged q/k/v).
// ---------------------------------------------------------------------------
#define GEMM_SMEM (2 * 32768)

template <int NOUT>
__global__ __launch_bounds__(256, 2) void gemm_mma_kernel(
    const __nv_bfloat16* __restrict__ Ah, const __nv_bfloat16* __restrict__ Al,
    const __nv_bfloat16* __restrict__ Bh_, const __nv_bfloat16* __restrict__ Bl_,
    float* __restrict__ C0, float* __restrict__ C1, float* __restrict__ C2)
{
    extern __shared__ char sm[];
    const uint32_t sbase = smem_u32(sm);

    const int tid = threadIdx.x;
    const int wid = tid >> 5, lane = tid & 31;
    const int wm = wid & 1, wn = wid >> 1;
    const int m0 = blockIdx.y * 128, n0 = blockIdx.x * 128;

    const __nv_bfloat16* Bh = Bh_;
    const __nv_bfloat16* Bl = Bl_;
    float* C = C0;
    if (NOUT == 3) {
        const size_t woff = (size_t)blockIdx.z * DM * DM;
        Bh = Bh_ + woff;
        Bl = Bl_ + woff;
        C = (blockIdx.z == 0) ? C0 : (blockIdx.z == 1) ? C1 : C2;
    }

    const int a_row = ((lane >> 3) & 1) * 8 + (lane & 7);
    const int a_kb  = (lane >> 4) * 16;
    const int l15 = lane & 15;
    const int b_row = l15 & 7;
    const int b_kb  = (l15 >> 3) * 16;

    const int r_0 = tid >> 2, kb_0 = tid & 3;
    const int r_1 = (tid + 256) >> 2, kb_1 = (tid + 256) & 3;
    const uint32_t so_0 = SWZ64(r_0 * 64 + kb_0 * 16);
    const uint32_t so_1 = SWZ64(r_1 * 64 + kb_1 * 16);

    float c[4][4][4] = {};

#define GEMM_ISSUE(kc, s) do {                                                  \
    const int _k0 = (kc) * 32;                                                  \
    const uint32_t _b = sbase + (s) * 32768;                                    \
    const size_t _ga0 = (size_t)(m0 + r_0) * DM + _k0 + kb_0 * 8;               \
    const size_t _ga1 = (size_t)(m0 + r_1) * DM + _k0 + kb_1 * 8;               \
    const size_t _gb0 = (size_t)(n0 + r_0) * DM + _k0 + kb_0 * 8;               \
    const size_t _gb1 = (size_t)(n0 + r_1) * DM + _k0 + kb_1 * 8;               \
    cpa16(_b + so_0,             Ah + _ga0);                                    \
    cpa16(_b + so_1,             Ah + _ga1);                                    \
    cpa16(_b + 8192  + so_0,     Al + _ga0);                                    \
    cpa16(_b + 8192  + so_1,     Al + _ga1);                                    \
    cpa16(_b + 16384 + so_0,     Bh + _gb0);                                    \
    cpa16(_b + 16384 + so_1,     Bh + _gb1);                                    \
    cpa16(_b + 24576 + so_0,     Bl + _gb0);                                    \
    cpa16(_b + 24576 + so_1,     Bl + _gb1);                                    \
    CPA_COMMIT();                                                               \
} while (0)

    GEMM_ISSUE(0, 0);

    for (int kc = 0; kc < 32; kc++) {
        CPA_WAIT0();
        __syncthreads();
        if (kc < 31) GEMM_ISSUE(kc + 1, (kc + 1) & 1);

        const uint32_t uAh = sbase + (kc & 1) * 32768;
        const uint32_t uAl = uAh + 8192;
        const uint32_t uBh = uAh + 16384;
        const uint32_t uBl = uAh + 24576;

#pragma unroll
        for (int ks = 0; ks < 2; ks++) {
            uint32_t bh[4][2], bl[4][2];
#pragma unroll
            for (int nt = 0; nt < 4; nt++) {
                const uint32_t bo =
                    SWZ64((wn * 32 + nt * 8 + b_row) * 64 + ks * 32 + b_kb);
                ldsm2(uBh + bo, bh[nt]);
                ldsm2(uBl + bo, bl[nt]);
            }
#pragma unroll
            for (int mt = 0; mt < 4; mt++) {
                uint32_t ah[4], al[4];
                const uint32_t ao =
                    SWZ64((wm * 64 + mt * 16 + a_row) * 64 + ks * 32 + a_kb);
                ldsm4(uAh + ao, ah);
                ldsm4(uAl + ao, al);
#pragma unroll
                for (int nt = 0; nt < 4; nt++) {
                    mma_bf16(c[mt][nt], ah, bh[nt]);
                    mma_bf16(c[mt][nt], ah, bl[nt]);
                    mma_bf16(c[mt][nt], al, bh[nt]);
                }
            }
        }
        __syncthreads();
    }

    const int gq = lane >> 2, tq = lane & 3;
#pragma unroll
    for (int mt = 0; mt < 4; mt++) {
#pragma unroll
        for (int nt = 0; nt < 4; nt++) {
            const int row = m0 + wm * 64 + mt * 16 + gq;
            const int col = n0 + wn * 32 + nt * 8 + tq * 2;
            *(float2*)&C[(size_t)row * DM + col] =
                make_float2(c[mt][nt][0], c[mt][nt][1]);
            *(float2*)&C[(size_t)(row + 8) * DM + col] =
                make_float2(c[mt][nt][2], c[mt][nt][3]);
        }
    }
}

// ---------------------------------------------------------------------------
// Tensor-core causal flash attention. PROVEN config: 1 CTA/SM, regs
// unconstrained. P pack interleaved with PV (keeps live set small).
// ---------------------------------------------------------------------------
#define ATTN_SMEM (32768 + 2 * 32768)

__global__ __launch_bounds__(256, 1) void attn_mma_kernel(
    const __nv_bfloat16* __restrict__ qh, const __nv_bfloat16* __restrict__ ql,
    const __nv_bfloat16* __restrict__ kh, const __nv_bfloat16* __restrict__ kl,
    const __nv_bfloat16* __restrict__ vh, const __nv_bfloat16* __restrict__ vl,
    __nv_bfloat16* __restrict__ oh, __nv_bfloat16* __restrict__ ol)
{
    extern __shared__ char sm[];
    const uint32_t sb = smem_u32(sm);
    const uint32_t uQh = sb, uQl = sb + 16384;

    const int tid = threadIdx.x, wid = tid >> 5, lane = tid & 31;
    const int h = blockIdx.y;
    const int qi = gridDim.x - 1 - blockIdx.x;
    const int q0 = qi * 128;
    const size_t hbase = (size_t)h * N_TOK * DH;  // bf16 elems

    // ---- load Q hi/lo tiles (each 128 rows x 128B), swizzled ----
    {
        const char* gqh = (const char*)(qh + hbase + (size_t)q0 * DH);
        const char* gql = (const char*)(ql + hbase + (size_t)q0 * DH);
#pragma unroll
        for (int it = 0; it < 4; it++) {
            int idx = tid + 256 * it;
            int row = idx >> 3, ck = idx & 7;
            uint32_t so = SWZ128(row * 128 + ck * 16);
            *(uint4*)(sm + so) = *(const uint4*)(gqh + row * 128 + ck * 16);
            *(uint4*)(sm + 16384 + so) = *(const uint4*)(gql + row * 128 + ck * 16);
        }
    }

    const int kr0 = tid >> 3, kc0 = tid & 7;
    const int kr1 = (tid + 256) >> 3, kc1 = (tid + 256) & 7;
    const uint32_t kso0 = SWZ128(kr0 * 128 + kc0 * 16);
    const uint32_t kso1 = SWZ128(kr1 * 128 + kc1 * 16);

#define ATTN_ISSUE(jt, s) do {                                                  \
    const size_t _tb = hbase + (size_t)((jt) * 64) * DH;                        \
    const char* _kh = (const char*)(kh + _tb);                                  \
    const char* _kl = (const char*)(kl + _tb);                                  \
    const char* _vh = (const char*)(vh + _tb);                                  \
    const char* _vl = (const char*)(vl + _tb);                                  \
    const uint32_t _b = sb + 32768 + (s) * 32768;                               \
    cpa16(_b + kso0,          _kh + kr0 * 128 + kc0 * 16);                      \
    cpa16(_b + kso1,          _kh + kr1 * 128 + kc1 * 16);                      \
    cpa16(_b + 8192 + kso0,   _kl + kr0 * 128 + kc0 * 16);                      \
    cpa16(_b + 8192 + kso1,   _kl + kr1 * 128 + kc1 * 16);                      \
    cpa16(_b + 16384 + kso0,  _vh + kr0 * 128 + kc0 * 16);                      \
    cpa16(_b + 16384 + kso1,  _vh + kr1 * 128 + kc1 * 16);                      \
    cpa16(_b + 24576 + kso0,  _vl + kr0 * 128 + kc0 * 16);                      \
    cpa16(_b + 24576 + kso1,  _vl + kr1 * 128 + kc1 * 16);                      \
    CPA_COMMIT();                                                               \
} while (0)

    float m_run[2] = {-1e30f, -1e30f};
    float l_run[2] = {0.0f, 0.0f};
    float o[8][4] = {};

    const int row_lo = q0 + wid * 16 + (lane >> 2);
    const int njt = 2 * qi + 2;

    ATTN_ISSUE(0, 0);

    for (int jt = 0; jt < njt; jt++) {
        const int kv0 = jt * 64;
        CPA_WAIT0();
        __syncthreads();
        if (jt + 1 < njt) ATTN_ISSUE(jt + 1, (jt + 1) & 1);

        // warps 0-3 (rows q0..q0+63): last kv tile fully masked — skip
        if (wid < 4 && jt == njt - 1) continue;

        const uint32_t uKh = sb + 32768 + (jt & 1) * 32768;
        const uint32_t uKl = uKh + 8192;
        const uint32_t uVh = uKh + 16384;
        const uint32_t uVl = uKh + 24576;

        // ---- S = Qh*Kh + Qh*Kl + Ql*Kh  (m16 x n64, k=64) ----
        float c[8][4] = {};
#pragma unroll
        for (int ks = 0; ks < 4; ks++) {
            uint32_t ah[4], al[4];
            const uint32_t ao = SWZ128(
                (wid * 16 + ((lane >> 3) & 1) * 8 + (lane & 7)) * 128 +
                ks * 32 + (lane >> 4) * 16);
            ldsm4(uQh + ao, ah);
            ldsm4(uQl + ao, al);
#pragma unroll
            for (int np = 0; np < 4; np++) {
                uint32_t bh[4], bl[4];
                const uint32_t bo = SWZ128(
                    (np * 16 + (lane >> 4) * 8 + (lane & 7)) * 128 +
                    ks * 32 + ((lane >> 3) & 1) * 16);
                ldsm4(uKh + bo, bh);
                ldsm4(uKl + bo, bl);
                mma_bf16(c[2 * np + 0], ah, bh + 0);
                mma_bf16(c[2 * np + 0], ah, bl + 0);
                mma_bf16(c[2 * np + 0], al, bh + 0);
                mma_bf16(c[2 * np + 1], ah, bh + 2);
                mma_bf16(c[2 * np + 1], ah, bl + 2);
                mma_bf16(c[2 * np + 1], al, bh + 2);
            }
        }

        // ---- online softmax in registers ----
        float mx[2] = {-1e30f, -1e30f};
#pragma unroll
        for (int nt = 0; nt < 8; nt++) {
#pragma unroll
            for (int j = 0; j < 4; j++) {
                const int half = j >> 1, i = j & 1;
                const int key = kv0 + nt * 8 + (lane & 3) * 2 + i;
                float sv = c[nt][j] * 8.0f;
                if (key > row_lo + 8 * half) sv = -1e30f;
                c[nt][j] = sv;
                mx[half] = fmaxf(mx[half], sv);
            }
        }
#pragma unroll
        for (int half = 0; half < 2; half++) {
            mx[half] = fmaxf(mx[half], __shfl_xor_sync(0xffffffffu, mx[half], 1));
            mx[half] = fmaxf(mx[half], __shfl_xor_sync(0xffffffffu, mx[half], 2));
            float m_new = fmaxf(m_run[half], mx[half]);
            float fac = __expf(m_run[half] - m_new);
            m_run[half] = m_new;
            l_run[half] *= fac;
#pragma unroll
            for (int nt = 0; nt < 8; nt++) {
                o[nt][half * 2 + 0] *= fac;
                o[nt][half * 2 + 1] *= fac;
            }
        }
        float ts[2] = {0.0f, 0.0f};
#pragma unroll
        for (int nt = 0; nt < 8; nt++) {
#pragma unroll
            for (int j = 0; j < 4; j++) {
                float pv = __expf(c[nt][j] - m_run[j >> 1]);
                c[nt][j] = pv;
                ts[j >> 1] += pv;
            }
        }
#pragma unroll
        for (int half = 0; half < 2; half++) {
            ts[half] += __shfl_xor_sync(0xffffffffu, ts[half], 1);
            ts[half] += __shfl_xor_sync(0xffffffffu, ts[half], 2);
            l_run[half] += ts[half];
        }

        // ---- PV interleaved with pack (short ph/pl live range) ----
#pragma unroll
        for (int kt = 0; kt < 4; kt++) {
            uint32_t ph[4], pl[4];
            {
                const float* e = c[2 * kt];
                const float* f = c[2 * kt + 1];
                ph[0] = pack2(e[0], e[1]);
                ph[1] = pack2(e[2], e[3]);
                ph[2] = pack2(f[0], f[1]);
                ph[3] = pack2(f[2], f[3]);
                pl[0] = pack2(e[0] - bfr(e[0]), e[1] - bfr(e[1]));
                pl[1] = pack2(e[2] - bfr(e[2]), e[3] - bfr(e[3]));
                pl[2] = pack2(f[0] - bfr(f[0]), f[1] - bfr(f[1]));
                pl[3] = pack2(f[2] - bfr(f[2]), f[3] - bfr(f[3]));
            }
#pragma unroll
            for (int dp = 0; dp < 4; dp++) {
                uint32_t vhf[4], vlf[4];
                const uint32_t vo = SWZ128(
                    (kt * 16 + (lane & 15)) * 128 +
                    dp * 32 + (lane >> 4) * 16);
                ldsm4t(uVh + vo, vhf);
                ldsm4t(uVl + vo, vlf);
                mma_bf16(o[2 * dp + 0], ph, vhf + 0);
                mma_bf16(o[2 * dp + 0], ph, vlf + 0);
                mma_bf16(o[2 * dp + 0], pl, vhf + 0);
                mma_bf16(o[2 * dp + 1], ph, vhf + 2);
                mma_bf16(o[2 * dp + 1], ph, vlf + 2);
                mma_bf16(o[2 * dp + 1], pl, vhf + 2);
            }
        }
    }

    // ---- epilogue: O /= l, split to bf16 hi/lo, write [tok][1024] ----
    const float inv0 = 1.0f / l_run[0];
    const float inv1 = 1.0f / l_run[1];
    uint32_t* poh = (uint32_t*)oh;
    uint32_t* pol = (uint32_t*)ol;
#pragma unroll
    for (int dt = 0; dt < 8; dt++) {
        const int col = h * DH + dt * 8 + (lane & 3) * 2;
        float a0 = o[dt][0] * inv0, a1 = o[dt][1] * inv0;
        float b0 = o[dt][2] * inv1, b1 = o[dt][3] * inv1;
        const size_t i0 = ((size_t)row_lo * DM + col) >> 1;
        const size_t i1 = ((size_t)(row_lo + 8) * DM + col) >> 1;
        poh[i0] = pack2(a0, a1);
        pol[i0] = pack2(a0 - bfr(a0), a1 - bfr(a1));
        poh[i1] = pack2(b0, b1);
        pol[i1] = pack2(b0 - bfr(b0), b1 - bfr(b1));
    }
}

// ---------------------------------------------------------------------------
extern "C" void kernel_launch(void* const* d_in, const int* in_sizes, int n_in,
                              void* d_out, int out_size)
{
    const float* x  = (const float*)d_in[0];
    const float* Wq = (const float*)d_in[1];
    const float* Wk = (const float*)d_in[2];
    const float* Wv = (const float*)d_in[3];
    const float* Wo = (const float*)d_in[4];
    float* out = (float*)d_out;

    float *q, *k, *v;
    cudaGetSymbolAddress((void**)&q, g_q);
    cudaGetSymbolAddress((void**)&k, g_k);
    cudaGetSymbolAddress((void**)&v, g_v);
    __nv_bfloat16 *xh, *xl, *oh, *ol, *wth, *wtl;
    __nv_bfloat16 *qh, *ql, *kh, *kl, *vh, *vl;
    cudaGetSymbolAddress((void**)&xh, g_xh);
    cudaGetSymbolAddress((void**)&xl, g_xl);
    cudaGetSymbolAddress((void**)&oh, g_oh);
    cudaGetSymbolAddress((void**)&ol, g_ol);
    cudaGetSymbolAddress((void**)&wth, g_wth);
    cudaGetSymbolAddress((void**)&wtl, g_wtl);
    cudaGetSymbolAddress((void**)&qh, g_qh);
    cudaGetSymbolAddress((void**)&ql, g_ql);
    cudaGetSymbolAddress((void**)&kh, g_kh);
    cudaGetSymbolAddress((void**)&kl, g_kl);
    cudaGetSymbolAddress((void**)&vh, g_vh);
    cudaGetSymbolAddress((void**)&vl, g_vl);

    cudaFuncSetAttribute(gemm_mma_kernel<3>,
                         cudaFuncAttributeMaxDynamicSharedMemorySize, GEMM_SMEM);
    cudaFuncSetAttribute(gemm_mma_kernel<1>,
                         cudaFuncAttributeMaxDynamicSharedMemorySize, GEMM_SMEM);
    cudaFuncSetAttribute(attn_mma_kernel,
                         cudaFuncAttributeMaxDynamicSharedMemorySize, ATTN_SMEM);

    const int nvec = N_TOK * DM / 4;

    split_kernel<<<nvec / 256, 256>>>(x, xh, xl);
    tsplit_kernel<<<dim3(32, 32, 4), dim3(32, 8)>>>(Wq, Wk, Wv, Wo, wth, wtl);
    gemm_mma_kernel<3><<<dim3(DM / 128, N_TOK / 128, 3), 256, GEMM_SMEM>>>(
        xh, xl, wth, wtl, q, k, v);
    qkv_prep_kernel<<<N_TOK * NHEADS / 8, 256>>>(q, k, v, qh, ql, kh, kl, vh, vl);
    attn_mma_kernel<<<dim3(N_TOK / 128, NHEADS), 256, ATTN_SMEM>>>(qh, ql, kh, kl, vh, vl, oh, ol);
    gemm_mma_kernel<1><<<dim3(DM / 128, N_TOK / 128, 1), 256, GEMM_SMEM>>>(
        oh, ol, wth + 3 * (size_t)DM * DM, wtl + 3 * (size_t)DM * DM, out, nullptr, nullptr);
}

// round 13
// speedup vs baseline: 1.1099x; 1.0217x over previous
#include <cuda_runtime.h>
#include <cuda_bf16.h>
#include <cstdint>
#include <math.h>

#define N_TOK 4096
#define DM 1024
#define NHEADS 16
#define DH 64

// ---------------------------------------------------------------------------
// Scratch (allocation-free rule: __device__ globals)
// ---------------------------------------------------------------------------
__device__ __nv_bfloat16 g_xh[N_TOK * DM];
__device__ __nv_bfloat16 g_xl[N_TOK * DM];
__device__ __nv_bfloat16 g_oh[N_TOK * DM];
__device__ __nv_bfloat16 g_ol[N_TOK * DM];
__device__ __nv_bfloat16 g_wth[4 * DM * DM];  // W^T hi: [w][n][k]
__device__ __nv_bfloat16 g_wtl[4 * DM * DM];  // W^T lo
// normalized/split attention operands, [head][tok][64]
__device__ __nv_bfloat16 g_qh[N_TOK * DM];
__device__ __nv_bfloat16 g_ql[N_TOK * DM];
__device__ __nv_bfloat16 g_kh[N_TOK * DM];
__device__ __nv_bfloat16 g_kl[N_TOK * DM];
__device__ __nv_bfloat16 g_vh[N_TOK * DM];
__device__ __nv_bfloat16 g_vl[N_TOK * DM];

#define SWZ64(o)  ((o) ^ (((o) >> 3) & 0x30))
#define SWZ128(o) ((o) ^ (((o) >> 3) & 0x70))

__device__ __forceinline__ uint32_t smem_u32(const void* p) {
    uint32_t a;
    asm("{ .reg .u64 t; cvta.to.shared.u64 t, %1; cvt.u32.u64 %0, t; }"
        : "=r"(a) : "l"(p));
    return a;
}
__device__ __forceinline__ void cpa16(uint32_t dst, const void* src) {
    asm volatile("cp.async.cg.shared.global [%0], [%1], 16;"
                 :: "r"(dst), "l"(src));
}
#define CPA_COMMIT() asm volatile("cp.async.commit_group;" ::: "memory")
#define CPA_WAIT0()  asm volatile("cp.async.wait_group 0;" ::: "memory")

__device__ __forceinline__ void ldsm4(uint32_t addr, uint32_t r[4]) {
    asm volatile("ldmatrix.sync.aligned.m8n8.x4.shared.b16 {%0,%1,%2,%3}, [%4];"
                 : "=r"(r[0]), "=r"(r[1]), "=r"(r[2]), "=r"(r[3]) : "r"(addr));
}
__device__ __forceinline__ void ldsm4t(uint32_t addr, uint32_t r[4]) {
    asm volatile("ldmatrix.sync.aligned.m8n8.x4.trans.shared.b16 {%0,%1,%2,%3}, [%4];"
                 : "=r"(r[0]), "=r"(r[1]), "=r"(r[2]), "=r"(r[3]) : "r"(addr));
}
__device__ __forceinline__ void ldsm2(uint32_t addr, uint32_t r[2]) {
    asm volatile("ldmatrix.sync.aligned.m8n8.x2.shared.b16 {%0,%1}, [%2];"
                 : "=r"(r[0]), "=r"(r[1]) : "r"(addr));
}
__device__ __forceinline__ void mma_bf16(float c[4], const uint32_t a[4],
                                         const uint32_t b[2]) {
    asm volatile(
        "mma.sync.aligned.m16n8k16.row.col.f32.bf16.bf16.f32 "
        "{%0,%1,%2,%3}, {%4,%5,%6,%7}, {%8,%9}, {%0,%1,%2,%3};"
        : "+f"(c[0]), "+f"(c[1]), "+f"(c[2]), "+f"(c[3])
        : "r"(a[0]), "r"(a[1]), "r"(a[2]), "r"(a[3]), "r"(b[0]), "r"(b[1]));
}
__device__ __forceinline__ uint32_t pack2(float a, float b) {
    uint32_t r;
    asm("cvt.rn.bf16x2.f32 %0, %1, %2;" : "=r"(r) : "f"(b), "f"(a));
    return r;
}
__device__ __forceinline__ float bfr(float x) {
    return __bfloat162float(__float2bfloat16(x));
}

// ---------------------------------------------------------------------------
// Split fp32 -> (hi, lo) bf16, elementwise (for x).
// ---------------------------------------------------------------------------
__global__ __launch_bounds__(256) void split_kernel(
    const float* __restrict__ src, __nv_bfloat16* __restrict__ h,
    __nv_bfloat16* __restrict__ l)
{
    int i = blockIdx.x * 256 + threadIdx.x;
    float4 v = ((const float4*)src)[i];
    ((uint32_t*)h)[2 * i + 0] = pack2(v.x, v.y);
    ((uint32_t*)h)[2 * i + 1] = pack2(v.z, v.w);
    ((uint32_t*)l)[2 * i + 0] = pack2(v.x - bfr(v.x), v.y - bfr(v.y));
    ((uint32_t*)l)[2 * i + 1] = pack2(v.z - bfr(v.z), v.w - bfr(v.w));
}

// ---------------------------------------------------------------------------
// Transpose + split all 4 weight matrices: out[w][n][k] = split(W_w[k][n]).
// ---------------------------------------------------------------------------
__global__ __launch_bounds__(256) void tsplit_kernel(
    const float* __restrict__ W0, const float* __restrict__ W1,
    const float* __restrict__ W2, const float* __restrict__ W3,
    __nv_bfloat16* __restrict__ H, __nv_bfloat16* __restrict__ L)
{
    const float* W = (blockIdx.z == 0) ? W0 : (blockIdx.z == 1) ? W1
                   : (blockIdx.z == 2) ? W2 : W3;
    __nv_bfloat16* h = H + (size_t)blockIdx.z * DM * DM;
    __nv_bfloat16* l = L + (size_t)blockIdx.z * DM * DM;
    __shared__ float t[32][33];
    const int bx = blockIdx.x * 32;
    const int by = blockIdx.y * 32;
    const int tx = threadIdx.x;
    for (int j = threadIdx.y; j < 32; j += 8)
        t[j][tx] = W[(size_t)(by + j) * DM + bx + tx];
    __syncthreads();
    for (int j = threadIdx.y; j < 32; j += 8) {
        float v = t[tx][j];
        __nv_bfloat16 hv = __float2bfloat16(v);
        __nv_bfloat16 lv = __float2bfloat16(v - __bfloat162float(hv));
        size_t idx = (size_t)(bx + j) * DM + by + tx;
        h[idx] = hv;
        l[idx] = lv;
    }
}

// ---------------------------------------------------------------------------
// HMMA split-bf16 GEMM with cp.async double buffering.
// CTA 128x128, BK=32, 8 warps (2m x 4n).
// NOUT == 3 (QKV): blockIdx.z selects weight slice; epilogue FUSES l2norm
//   (z<2) + hi/lo bf16 split and writes [head][tok][64] attention operands.
// NOUT == 1: plain fp32 C write (final projection).
// ---------------------------------------------------------------------------
#define GEMM_SMEM (2 * 32768)

template <int NOUT>
__global__ __launch_bounds__(256, 2) void gemm_mma_kernel(
    const __nv_bfloat16* __restrict__ Ah, const __nv_bfloat16* __restrict__ Al,
    const __nv_bfloat16* __restrict__ Bh_, const __nv_bfloat16* __restrict__ Bl_,
    float* __restrict__ Cout,
    __nv_bfloat16* __restrict__ qh, __nv_bfloat16* __restrict__ ql,
    __nv_bfloat16* __restrict__ kh, __nv_bfloat16* __restrict__ kl,
    __nv_bfloat16* __restrict__ vh, __nv_bfloat16* __restrict__ vl)
{
    extern __shared__ char sm[];
    const uint32_t sbase = smem_u32(sm);

    const int tid = threadIdx.x;
    const int wid = tid >> 5, lane = tid & 31;
    const int wm = wid & 1, wn = wid >> 1;
    const int m0 = blockIdx.y * 128, n0 = blockIdx.x * 128;

    const __nv_bfloat16* Bh = Bh_;
    const __nv_bfloat16* Bl = Bl_;
    if (NOUT == 3) {
        const size_t woff = (size_t)blockIdx.z * DM * DM;
        Bh = Bh_ + woff;
        Bl = Bl_ + woff;
    }

    const int a_row = ((lane >> 3) & 1) * 8 + (lane & 7);
    const int a_kb  = (lane >> 4) * 16;
    const int l15 = lane & 15;
    const int b_row = l15 & 7;
    const int b_kb  = (l15 >> 3) * 16;

    const int r_0 = tid >> 2, kb_0 = tid & 3;
    const int r_1 = (tid + 256) >> 2, kb_1 = (tid + 256) & 3;
    const uint32_t so_0 = SWZ64(r_0 * 64 + kb_0 * 16);
    const uint32_t so_1 = SWZ64(r_1 * 64 + kb_1 * 16);

    float c[4][4][4] = {};

#define GEMM_ISSUE(kc, s) do {                                                  \
    const int _k0 = (kc) * 32;                                                  \
    const uint32_t _b = sbase + (s) * 32768;                                    \
    const size_t _ga0 = (size_t)(m0 + r_0) * DM + _k0 + kb_0 * 8;               \
    const size_t _ga1 = (size_t)(m0 + r_1) * DM + _k0 + kb_1 * 8;               \
    const size_t _gb0 = (size_t)(n0 + r_0) * DM + _k0 + kb_0 * 8;               \
    const size_t _gb1 = (size_t)(n0 + r_1) * DM + _k0 + kb_1 * 8;               \
    cpa16(_b + so_0,             Ah + _ga0);                                    \
    cpa16(_b + so_1,             Ah + _ga1);                                    \
    cpa16(_b + 8192  + so_0,     Al + _ga0);                                    \
    cpa16(_b + 8192  + so_1,     Al + _ga1);                                    \
    cpa16(_b + 16384 + so_0,     Bh + _gb0);                                    \
    cpa16(_b + 16384 + so_1,     Bh + _gb1);                                    \
    cpa16(_b + 24576 + so_0,     Bl + _gb0);                                    \
    cpa16(_b + 24576 + so_1,     Bl + _gb1);                                    \
    CPA_COMMIT();                                                               \
} while (0)

    GEMM_ISSUE(0, 0);

    for (int kc = 0; kc < 32; kc++) {
        CPA_WAIT0();
        __syncthreads();
        if (kc < 31) GEMM_ISSUE(kc + 1, (kc + 1) & 1);

        const uint32_t uAh = sbase + (kc & 1) * 32768;
        const uint32_t uAl = uAh + 8192;
        const uint32_t uBh = uAh + 16384;
        const uint32_t uBl = uAh + 24576;

#pragma unroll
        for (int ks = 0; ks < 2; ks++) {
            uint32_t bh[4][2], bl[4][2];
#pragma unroll
            for (int nt = 0; nt < 4; nt++) {
                const uint32_t bo =
                    SWZ64((wn * 32 + nt * 8 + b_row) * 64 + ks * 32 + b_kb);
                ldsm2(uBh + bo, bh[nt]);
                ldsm2(uBl + bo, bl[nt]);
            }
#pragma unroll
            for (int mt = 0; mt < 4; mt++) {
                uint32_t ah[4], al[4];
                const uint32_t ao =
                    SWZ64((wm * 64 + mt * 16 + a_row) * 64 + ks * 32 + a_kb);
                ldsm4(uAh + ao, ah);
                ldsm4(uAl + ao, al);
#pragma unroll
                for (int nt = 0; nt < 4; nt++) {
                    mma_bf16(c[mt][nt], ah, bh[nt]);
                    mma_bf16(c[mt][nt], ah, bl[nt]);
                    mma_bf16(c[mt][nt], al, bh[nt]);
                }
            }
        }
        __syncthreads();
    }

    const int gq = lane >> 2, tq = lane & 3;

    if (NOUT == 1) {
#pragma unroll
        for (int mt = 0; mt < 4; mt++) {
#pragma unroll
            for (int nt = 0; nt < 4; nt++) {
                const int row = m0 + wm * 64 + mt * 16 + gq;
                const int col = n0 + wn * 32 + nt * 8 + tq * 2;
                *(float2*)&Cout[(size_t)row * DM + col] =
                    make_float2(c[mt][nt][0], c[mt][nt][1]);
                *(float2*)&Cout[(size_t)(row + 8) * DM + col] =
                    make_float2(c[mt][nt][2], c[mt][nt][3]);
            }
        }
        return;
    }

    // ---- fused epilogue (NOUT == 3): l2norm (z<2) + split + [head][tok] ----
    const int z = blockIdx.z;
    __nv_bfloat16* H = (z == 0) ? qh : (z == 1) ? kh : vh;
    __nv_bfloat16* L = (z == 0) ? ql : (z == 1) ? kl : vl;

    float inv_[4][2];
#pragma unroll
    for (int mt = 0; mt < 4; mt++) { inv_[mt][0] = 1.0f; inv_[mt][1] = 1.0f; }

    if (z < 2) {
        // per-row sum of squares over this head's 64 cols (warp pair wn^1)
        float* rs = (float*)sm;  // [head(2)][rowlocal(128)][wnhalf(2)]
#pragma unroll
        for (int mt = 0; mt < 4; mt++) {
#pragma unroll
            for (int half = 0; half < 2; half++) {
                float s = 0.0f;
#pragma unroll
                for (int nt = 0; nt < 4; nt++) {
                    float a = c[mt][nt][half * 2 + 0];
                    float b = c[mt][nt][half * 2 + 1];
                    s += a * a + b * b;
                }
                s += __shfl_xor_sync(0xffffffffu, s, 1);
                s += __shfl_xor_sync(0xffffffffu, s, 2);
                if (tq == 0) {
                    const int rowl = wm * 64 + mt * 16 + gq + half * 8;
                    rs[(wn >> 1) * 256 + rowl * 2 + (wn & 1)] = s;
                }
            }
        }
        __syncthreads();
#pragma unroll
        for (int mt = 0; mt < 4; mt++) {
#pragma unroll
            for (int half = 0; half < 2; half++) {
                const int rowl = wm * 64 + mt * 16 + gq + half * 8;
                float ss = rs[(wn >> 1) * 256 + rowl * 2 + 0] +
                           rs[(wn >> 1) * 256 + rowl * 2 + 1];
                inv_[mt][half] = 1.0f / fmaxf(sqrtf(ss), 1e-12f);
            }
        }
    }

    const int head = (n0 >> 6) + (wn >> 1);
    const int dh = (wn & 1) * 32 + tq * 2;
    uint32_t* PH = (uint32_t*)H;
    uint32_t* PL = (uint32_t*)L;
#pragma unroll
    for (int mt = 0; mt < 4; mt++) {
        const int tok0 = m0 + wm * 64 + mt * 16 + gq;
        const float i0 = inv_[mt][0], i1 = inv_[mt][1];
#pragma unroll
        for (int nt = 0; nt < 4; nt++) {
            float a0 = c[mt][nt][0] * i0, a1 = c[mt][nt][1] * i0;
            float b0 = c[mt][nt][2] * i1, b1 = c[mt][nt][3] * i1;
            const size_t i0x =
                (((size_t)head * N_TOK + tok0) * DH + dh + nt * 8) >> 1;
            const size_t i1x = i0x + 4 * DH / 2 * 2;  // +8 rows = +8*64/2 u32
            PH[i0x] = pack2(a0, a1);
            PL[i0x] = pack2(a0 - bfr(a0), a1 - bfr(a1));
            PH[i1x] = pack2(b0, b1);
            PL[i1x] = pack2(b0 - bfr(b0), b1 - bfr(b1));
        }
    }
}

// ---------------------------------------------------------------------------
// Tensor-core causal flash attention. 1 CTA/SM, Q fragments hoisted into
// registers, log2-domain online softmax (bare EX2), cp.async KV pipeline.
// ---------------------------------------------------------------------------
#define ATTN_SMEM (32768 + 2 * 32768)
#define SCALE_L2E 11.541560327111707f  /* 8 * log2(e) */

__global__ __launch_bounds__(256, 1) void attn_mma_kernel(
    const __nv_bfloat16* __restrict__ qh, const __nv_bfloat16* __restrict__ ql,
    const __nv_bfloat16* __restrict__ kh, const __nv_bfloat16* __restrict__ kl,
    const __nv_bfloat16* __restrict__ vh, const __nv_bfloat16* __restrict__ vl,
    __nv_bfloat16* __restrict__ oh, __nv_bfloat16* __restrict__ ol)
{
    extern __shared__ char sm[];
    const uint32_t sb = smem_u32(sm);
    const uint32_t uQh = sb, uQl = sb + 16384;

    const int tid = threadIdx.x, wid = tid >> 5, lane = tid & 31;
    const int h = blockIdx.y;
    const int qi = gridDim.x - 1 - blockIdx.x;
    const int q0 = qi * 128;
    const size_t hbase = (size_t)h * N_TOK * DH;  // bf16 elems

    // ---- load Q hi/lo tiles, swizzled ----
    {
        const char* gqh = (const char*)(qh + hbase + (size_t)q0 * DH);
        const char* gql = (const char*)(ql + hbase + (size_t)q0 * DH);
#pragma unroll
        for (int it = 0; it < 4; it++) {
            int idx = tid + 256 * it;
            int row = idx >> 3, ck = idx & 7;
            uint32_t so = SWZ128(row * 128 + ck * 16);
            *(uint4*)(sm + so) = *(const uint4*)(gqh + row * 128 + ck * 16);
            *(uint4*)(sm + 16384 + so) = *(const uint4*)(gql + row * 128 + ck * 16);
        }
    }

    const int kr0 = tid >> 3, kc0 = tid & 7;
    const int kr1 = (tid + 256) >> 3, kc1 = (tid + 256) & 7;
    const uint32_t kso0 = SWZ128(kr0 * 128 + kc0 * 16);
    const uint32_t kso1 = SWZ128(kr1 * 128 + kc1 * 16);

#define ATTN_ISSUE(jt, s) do {                                                  \
    const size_t _tb = hbase + (size_t)((jt) * 64) * DH;                        \
    const char* _kh = (const char*)(kh + _tb);                                  \
    const char* _kl = (const char*)(kl + _tb);                                  \
    const char* _vh = (const char*)(vh + _tb);                                  \
    const char* _vl = (const char*)(vl + _tb);                                  \
    const uint32_t _b = sb + 32768 + (s) * 32768;                               \
    cpa16(_b + kso0,          _kh + kr0 * 128 + kc0 * 16);                      \
    cpa16(_b + kso1,          _kh + kr1 * 128 + kc1 * 16);                      \
    cpa16(_b + 8192 + kso0,   _kl + kr0 * 128 + kc0 * 16);                      \
    cpa16(_b + 8192 + kso1,   _kl + kr1 * 128 + kc1 * 16);                      \
    cpa16(_b + 16384 + kso0,  _vh + kr0 * 128 + kc0 * 16);                      \
    cpa16(_b + 16384 + kso1,  _vh + kr1 * 128 + kc1 * 16);                      \
    cpa16(_b + 24576 + kso0,  _vl + kr0 * 128 + kc0 * 16);                      \
    cpa16(_b + 24576 + kso1,  _vl + kr1 * 128 + kc1 * 16);                      \
    CPA_COMMIT();                                                               \
} while (0)

    ATTN_ISSUE(0, 0);

    // ---- hoist Q fragments into registers (tile-invariant) ----
    __syncthreads();
    uint32_t qfh[4][4], qfl[4][4];
#pragma unroll
    for (int ks = 0; ks < 4; ks++) {
        const uint32_t ao = SWZ128(
            (wid * 16 + ((lane >> 3) & 1) * 8 + (lane & 7)) * 128 +
            ks * 32 + (lane >> 4) * 16);
        ldsm4(uQh + ao, qfh[ks]);
        ldsm4(uQl + ao, qfl[ks]);
    }

    float m_run[2] = {-1e30f, -1e30f};   // log2 domain
    float l_run[2] = {0.0f, 0.0f};
    float o[8][4] = {};

    const int row_lo = q0 + wid * 16 + (lane >> 2);
    const int njt = 2 * qi + 2;

    for (int jt = 0; jt < njt; jt++) {
        const int kv0 = jt * 64;
        CPA_WAIT0();
        __syncthreads();
        if (jt + 1 < njt) ATTN_ISSUE(jt + 1, (jt + 1) & 1);

        // warps 0-3 (rows q0..q0+63): last kv tile fully masked — skip
        if (wid < 4 && jt == njt - 1) continue;

        const uint32_t uKh = sb + 32768 + (jt & 1) * 32768;
        const uint32_t uKl = uKh + 8192;
        const uint32_t uVh = uKh + 16384;
        const uint32_t uVl = uKh + 24576;

        // ---- S = Qh*Kh + Qh*Kl + Ql*Kh  (m16 x n64, k=64) ----
        float c[8][4] = {};
#pragma unroll
        for (int ks = 0; ks < 4; ks++) {
#pragma unroll
            for (int np = 0; np < 4; np++) {
                uint32_t bh[4], bl[4];
                const uint32_t bo = SWZ128(
                    (np * 16 + (lane >> 4) * 8 + (lane & 7)) * 128 +
                    ks * 32 + ((lane >> 3) & 1) * 16);
                ldsm4(uKh + bo, bh);
                ldsm4(uKl + bo, bl);
                mma_bf16(c[2 * np + 0], qfh[ks], bh + 0);
                mma_bf16(c[2 * np + 0], qfh[ks], bl + 0);
                mma_bf16(c[2 * np + 0], qfl[ks], bh + 0);
                mma_bf16(c[2 * np + 1], qfh[ks], bh + 2);
                mma_bf16(c[2 * np + 1], qfh[ks], bl + 2);
                mma_bf16(c[2 * np + 1], qfl[ks], bh + 2);
            }
        }

        // ---- online softmax (log2 domain) ----
        float mx[2] = {-1e30f, -1e30f};
#pragma unroll
        for (int nt = 0; nt < 8; nt++) {
#pragma unroll
            for (int j = 0; j < 4; j++) {
                const int half = j >> 1, i = j & 1;
                const int key = kv0 + nt * 8 + (lane & 3) * 2 + i;
                float sv = c[nt][j] * SCALE_L2E;
                if (key > row_lo + 8 * half) sv = -1e30f;
                c[nt][j] = sv;
                mx[half] = fmaxf(mx[half], sv);
            }
        }
#pragma unroll
        for (int half = 0; half < 2; half++) {
            mx[half] = fmaxf(mx[half], __shfl_xor_sync(0xffffffffu, mx[half], 1));
            mx[half] = fmaxf(mx[half], __shfl_xor_sync(0xffffffffu, mx[half], 2));
            float m_new = fmaxf(m_run[half], mx[half]);
            float fac = exp2f(m_run[half] - m_new);
            m_run[half] = m_new;
            l_run[half] *= fac;
#pragma unroll
            for (int nt = 0; nt < 8; nt++) {
                o[nt][half * 2 + 0] *= fac;
                o[nt][half * 2 + 1] *= fac;
            }
        }
        float ts[2] = {0.0f, 0.0f};
#pragma unroll
        for (int nt = 0; nt < 8; nt++) {
#pragma unroll
            for (int j = 0; j < 4; j++) {
                float pv = exp2f(c[nt][j] - m_run[j >> 1]);
                c[nt][j] = pv;
                ts[j >> 1] += pv;
            }
        }
#pragma unroll
        for (int half = 0; half < 2; half++) {
            ts[half] += __shfl_xor_sync(0xffffffffu, ts[half], 1);
            ts[half] += __shfl_xor_sync(0xffffffffu, ts[half], 2);
            l_run[half] += ts[half];
        }

        // ---- PV interleaved with pack (short ph/pl live range) ----
#pragma unroll
        for (int kt = 0; kt < 4; kt++) {
            uint32_t ph[4], pl[4];
            {
                const float* e = c[2 * kt];
                const float* f = c[2 * kt + 1];
                ph[0] = pack2(e[0], e[1]);
                ph[1] = pack2(e[2], e[3]);
                ph[2] = pack2(f[0], f[1]);
                ph[3] = pack2(f[2], f[3]);
                pl[0] = pack2(e[0] - bfr(e[0]), e[1] - bfr(e[1]));
                pl[1] = pack2(e[2] - bfr(e[2]), e[3] - bfr(e[3]));
                pl[2] = pack2(f[0] - bfr(f[0]), f[1] - bfr(f[1]));
                pl[3] = pack2(f[2] - bfr(f[2]), f[3] - bfr(f[3]));
            }
#pragma unroll
            for (int dp = 0; dp < 4; dp++) {
                uint32_t vhf[4], vlf[4];
                const uint32_t vo = SWZ128(
                    (kt * 16 + (lane & 15)) * 128 +
                    dp * 32 + (lane >> 4) * 16);
                ldsm4t(uVh + vo, vhf);
                ldsm4t(uVl + vo, vlf);
                mma_bf16(o[2 * dp + 0], ph, vhf + 0);
                mma_bf16(o[2 * dp + 0], ph, vlf + 0);
                mma_bf16(o[2 * dp + 0], pl, vhf + 0);
                mma_bf16(o[2 * dp + 1], ph, vhf + 2);
                mma_bf16(o[2 * dp + 1], ph, vlf + 2);
                mma_bf16(o[2 * dp + 1], pl, vhf + 2);
            }
        }
    }

    // ---- epilogue: O /= l, split to bf16 hi/lo, write [tok][1024] ----
    const float inv0 = 1.0f / l_run[0];
    const float inv1 = 1.0f / l_run[1];
    uint32_t* poh = (uint32_t*)oh;
    uint32_t* pol = (uint32_t*)ol;
#pragma unroll
    for (int dt = 0; dt < 8; dt++) {
        const int col = h * DH + dt * 8 + (lane & 3) * 2;
        float a0 = o[dt][0] * inv0, a1 = o[dt][1] * inv0;
        float b0 = o[dt][2] * inv1, b1 = o[dt][3] * inv1;
        const size_t i0 = ((size_t)row_lo * DM + col) >> 1;
        const size_t i1 = ((size_t)(row_lo + 8) * DM + col) >> 1;
        poh[i0] = pack2(a0, a1);
        pol[i0] = pack2(a0 - bfr(a0), a1 - bfr(a1));
        poh[i1] = pack2(b0, b1);
        pol[i1] = pack2(b0 - bfr(b0), b1 - bfr(b1));
    }
}

// ---------------------------------------------------------------------------
extern "C" void kernel_launch(void* const* d_in, const int* in_sizes, int n_in,
                              void* d_out, int out_size)
{
    const float* x  = (const float*)d_in[0];
    const float* Wq = (const float*)d_in[1];
    const float* Wk = (const float*)d_in[2];
    const float* Wv = (const float*)d_in[3];
    const float* Wo = (const float*)d_in[4];
    float* out = (float*)d_out;

    __nv_bfloat16 *xh, *xl, *oh, *ol, *wth, *wtl;
    __nv_bfloat16 *qh, *ql, *kh, *kl, *vh, *vl;
    cudaGetSymbolAddress((void**)&xh, g_xh);
    cudaGetSymbolAddress((void**)&xl, g_xl);
    cudaGetSymbolAddress((void**)&oh, g_oh);
    cudaGetSymbolAddress((void**)&ol, g_ol);
    cudaGetSymbolAddress((void**)&wth, g_wth);
    cudaGetSymbolAddress((void**)&wtl, g_wtl);
    cudaGetSymbolAddress((void**)&qh, g_qh);
    cudaGetSymbolAddress((void**)&ql, g_ql);
    cudaGetSymbolAddress((void**)&kh, g_kh);
    cudaGetSymbolAddress((void**)&kl, g_kl);
    cudaGetSymbolAddress((void**)&vh, g_vh);
    cudaGetSymbolAddress((void**)&vl, g_vl);

    cudaFuncSetAttribute(gemm_mma_kernel<3>,
                         cudaFuncAttributeMaxDynamicSharedMemorySize, GEMM_SMEM);
    cudaFuncSetAttribute(gemm_mma_kernel<1>,
                         cudaFuncAttributeMaxDynamicSharedMemorySize, GEMM_SMEM);
    cudaFuncSetAttribute(attn_mma_kernel,
                         cudaFuncAttributeMaxDynamicSharedMemorySize, ATTN_SMEM);

    const int nvec = N_TOK * DM / 4;

    split_kernel<<<nvec / 256, 256>>>(x, xh, xl);
    tsplit_kernel<<<dim3(32, 32, 4), dim3(32, 8)>>>(Wq, Wk, Wv, Wo, wth, wtl);
    // merged q/k/v projection with fused l2norm + split epilogue
    gemm_mma_kernel<3><<<dim3(DM / 128, N_TOK / 128, 3), 256, GEMM_SMEM>>>(
        xh, xl, wth, wtl, nullptr, qh, ql, kh, kl, vh, vl);
    attn_mma_kernel<<<dim3(N_TOK / 128, NHEADS), 256, ATTN_SMEM>>>(
        qh, ql, kh, kl, vh, vl, oh, ol);
    gemm_mma_kernel<1><<<dim3(DM / 128, N_TOK / 128, 1), 256, GEMM_SMEM>>>(
        oh, ol, wth + 3 * (size_t)DM * DM, wtl + 3 * (size_t)DM * DM, out,
        nullptr, nullptr, nullptr, nullptr, nullptr, nullptr);
}

// round 15
// speedup vs baseline: 1.1352x; 1.0228x over previous
#include <cuda_runtime.h>
#include <cuda_bf16.h>
#include <cstdint>
#include <math.h>

#define N_TOK 4096
#define DM 1024
#define NHEADS 16
#define DH 64

// ---------------------------------------------------------------------------
// Scratch (allocation-free rule: __device__ globals)
// ---------------------------------------------------------------------------
__device__ __nv_bfloat16 g_xh[N_TOK * DM];
__device__ __nv_bfloat16 g_xl[N_TOK * DM];
__device__ __nv_bfloat16 g_oh[N_TOK * DM];
__device__ __nv_bfloat16 g_ol[N_TOK * DM];
__device__ __nv_bfloat16 g_wth[4 * DM * DM];  // W^T hi: [w][n][k]
__device__ __nv_bfloat16 g_wtl[4 * DM * DM];  // W^T lo
// normalized/split attention operands, [head][tok][64]
__device__ __nv_bfloat16 g_qh[N_TOK * DM];
__device__ __nv_bfloat16 g_ql[N_TOK * DM];
__device__ __nv_bfloat16 g_kh[N_TOK * DM];
__device__ __nv_bfloat16 g_kl[N_TOK * DM];
__device__ __nv_bfloat16 g_vh[N_TOK * DM];
__device__ __nv_bfloat16 g_vl[N_TOK * DM];

#define SWZ64(o)  ((o) ^ (((o) >> 3) & 0x30))
#define SWZ128(o) ((o) ^ (((o) >> 3) & 0x70))

__device__ __forceinline__ uint32_t smem_u32(const void* p) {
    uint32_t a;
    asm("{ .reg .u64 t; cvta.to.shared.u64 t, %1; cvt.u32.u64 %0, t; }"
        : "=r"(a) : "l"(p));
    return a;
}
__device__ __forceinline__ void cpa16(uint32_t dst, const void* src) {
    asm volatile("cp.async.cg.shared.global [%0], [%1], 16;"
                 :: "r"(dst), "l"(src));
}
#define CPA_COMMIT() asm volatile("cp.async.commit_group;" ::: "memory")
#define CPA_WAIT0()  asm volatile("cp.async.wait_group 0;" ::: "memory")

__device__ __forceinline__ void ldsm4(uint32_t addr, uint32_t r[4]) {
    asm volatile("ldmatrix.sync.aligned.m8n8.x4.shared.b16 {%0,%1,%2,%3}, [%4];"
                 : "=r"(r[0]), "=r"(r[1]), "=r"(r[2]), "=r"(r[3]) : "r"(addr));
}
__device__ __forceinline__ void ldsm4t(uint32_t addr, uint32_t r[4]) {
    asm volatile("ldmatrix.sync.aligned.m8n8.x4.trans.shared.b16 {%0,%1,%2,%3}, [%4];"
                 : "=r"(r[0]), "=r"(r[1]), "=r"(r[2]), "=r"(r[3]) : "r"(addr));
}
__device__ __forceinline__ void ldsm2(uint32_t addr, uint32_t r[2]) {
    asm volatile("ldmatrix.sync.aligned.m8n8.x2.shared.b16 {%0,%1}, [%2];"
                 : "=r"(r[0]), "=r"(r[1]) : "r"(addr));
}
__device__ __forceinline__ void mma_bf16(float c[4], const uint32_t a[4],
                                         const uint32_t b[2]) {
    asm volatile(
        "mma.sync.aligned.m16n8k16.row.col.f32.bf16.bf16.f32 "
        "{%0,%1,%2,%3}, {%4,%5,%6,%7}, {%8,%9}, {%0,%1,%2,%3};"
        : "+f"(c[0]), "+f"(c[1]), "+f"(c[2]), "+f"(c[3])
        : "r"(a[0]), "r"(a[1]), "r"(a[2]), "r"(a[3]), "r"(b[0]), "r"(b[1]));
}
__device__ __forceinline__ uint32_t pack2(float a, float b) {
    uint32_t r;
    asm("cvt.rn.bf16x2.f32 %0, %1, %2;" : "=r"(r) : "f"(b), "f"(a));
    return r;
}
__device__ __forceinline__ float bfr(float x) {
    return __bfloat162float(__float2bfloat16(x));
}

// ---------------------------------------------------------------------------
// Split fp32 -> (hi, lo) bf16, elementwise (for x).
// ---------------------------------------------------------------------------
__global__ __launch_bounds__(256) void split_kernel(
    const float* __restrict__ src, __nv_bfloat16* __restrict__ h,
    __nv_bfloat16* __restrict__ l)
{
    int i = blockIdx.x * 256 + threadIdx.x;
    float4 v = ((const float4*)src)[i];
    ((uint32_t*)h)[2 * i + 0] = pack2(v.x, v.y);
    ((uint32_t*)h)[2 * i + 1] = pack2(v.z, v.w);
    ((uint32_t*)l)[2 * i + 0] = pack2(v.x - bfr(v.x), v.y - bfr(v.y));
    ((uint32_t*)l)[2 * i + 1] = pack2(v.z - bfr(v.z), v.w - bfr(v.w));
}

// ---------------------------------------------------------------------------
// Transpose + split all 4 weight matrices: out[w][n][k] = split(W_w[k][n]).
// ---------------------------------------------------------------------------
__global__ __launch_bounds__(256) void tsplit_kernel(
    const float* __restrict__ W0, const float* __restrict__ W1,
    const float* __restrict__ W2, const float* __restrict__ W3,
    __nv_bfloat16* __restrict__ H, __nv_bfloat16* __restrict__ L)
{
    const float* W = (blockIdx.z == 0) ? W0 : (blockIdx.z == 1) ? W1
                   : (blockIdx.z == 2) ? W2 : W3;
    __nv_bfloat16* h = H + (size_t)blockIdx.z * DM * DM;
    __nv_bfloat16* l = L + (size_t)blockIdx.z * DM * DM;
    __shared__ float t[32][33];
    const int bx = blockIdx.x * 32;
    const int by = blockIdx.y * 32;
    const int tx = threadIdx.x;
    for (int j = threadIdx.y; j < 32; j += 8)
        t[j][tx] = W[(size_t)(by + j) * DM + bx + tx];
    __syncthreads();
    for (int j = threadIdx.y; j < 32; j += 8) {
        float v = t[tx][j];
        __nv_bfloat16 hv = __float2bfloat16(v);
        __nv_bfloat16 lv = __float2bfloat16(v - __bfloat162float(hv));
        size_t idx = (size_t)(bx + j) * DM + by + tx;
        h[idx] = hv;
        l[idx] = lv;
    }
}

// ---------------------------------------------------------------------------
// HMMA split-bf16 GEMM with cp.async double buffering.
// CTA 128x128, BK=32, 8 warps (2m x 4n).
// NOUT == 3 (QKV): blockIdx.z selects weight slice; epilogue FUSES l2norm
//   (z<2) + hi/lo bf16 split and writes [head][tok][64] attention operands.
// NOUT == 1: plain fp32 C write (final projection).
// ---------------------------------------------------------------------------
#define GEMM_SMEM (2 * 32768)

template <int NOUT>
__global__ __launch_bounds__(256, 2) void gemm_mma_kernel(
    const __nv_bfloat16* __restrict__ Ah, const __nv_bfloat16* __restrict__ Al,
    const __nv_bfloat16* __restrict__ Bh_, const __nv_bfloat16* __restrict__ Bl_,
    float* __restrict__ Cout,
    __nv_bfloat16* __restrict__ qh, __nv_bfloat16* __restrict__ ql,
    __nv_bfloat16* __restrict__ kh, __nv_bfloat16* __restrict__ kl,
    __nv_bfloat16* __restrict__ vh, __nv_bfloat16* __restrict__ vl)
{
    extern __shared__ char sm[];
    const uint32_t sbase = smem_u32(sm);

    const int tid = threadIdx.x;
    const int wid = tid >> 5, lane = tid & 31;
    const int wm = wid & 1, wn = wid >> 1;
    const int m0 = blockIdx.y * 128, n0 = blockIdx.x * 128;

    const __nv_bfloat16* Bh = Bh_;
    const __nv_bfloat16* Bl = Bl_;
    if (NOUT == 3) {
        const size_t woff = (size_t)blockIdx.z * DM * DM;
        Bh = Bh_ + woff;
        Bl = Bl_ + woff;
    }

    const int a_row = ((lane >> 3) & 1) * 8 + (lane & 7);
    const int a_kb  = (lane >> 4) * 16;
    const int l15 = lane & 15;
    const int b_row = l15 & 7;
    const int b_kb  = (l15 >> 3) * 16;

    const int r_0 = tid >> 2, kb_0 = tid & 3;
    const int r_1 = (tid + 256) >> 2, kb_1 = (tid + 256) & 3;
    const uint32_t so_0 = SWZ64(r_0 * 64 + kb_0 * 16);
    const uint32_t so_1 = SWZ64(r_1 * 64 + kb_1 * 16);

    float c[4][4][4] = {};

#define GEMM_ISSUE(kc, s) do {                                                  \
    const int _k0 = (kc) * 32;                                                  \
    const uint32_t _b = sbase + (s) * 32768;                                    \
    const size_t _ga0 = (size_t)(m0 + r_0) * DM + _k0 + kb_0 * 8;               \
    const size_t _ga1 = (size_t)(m0 + r_1) * DM + _k0 + kb_1 * 8;               \
    const size_t _gb0 = (size_t)(n0 + r_0) * DM + _k0 + kb_0 * 8;               \
    const size_t _gb1 = (size_t)(n0 + r_1) * DM + _k0 + kb_1 * 8;               \
    cpa16(_b + so_0,             Ah + _ga0);                                    \
    cpa16(_b + so_1,             Ah + _ga1);                                    \
    cpa16(_b + 8192  + so_0,     Al + _ga0);                                    \
    cpa16(_b + 8192  + so_1,     Al + _ga1);                                    \
    cpa16(_b + 16384 + so_0,     Bh + _gb0);                                    \
    cpa16(_b + 16384 + so_1,     Bh + _gb1);                                    \
    cpa16(_b + 24576 + so_0,     Bl + _gb0);                                    \
    cpa16(_b + 24576 + so_1,     Bl + _gb1);                                    \
    CPA_COMMIT();                                                               \
} while (0)

    GEMM_ISSUE(0, 0);

    for (int kc = 0; kc < 32; kc++) {
        CPA_WAIT0();
        __syncthreads();
        if (kc < 31) GEMM_ISSUE(kc + 1, (kc + 1) & 1);

        const uint32_t uAh = sbase + (kc & 1) * 32768;
        const uint32_t uAl = uAh + 8192;
        const uint32_t uBh = uAh + 16384;
        const uint32_t uBl = uAh + 24576;

#pragma unroll
        for (int ks = 0; ks < 2; ks++) {
            uint32_t bh[4][2], bl[4][2];
#pragma unroll
            for (int nt = 0; nt < 4; nt++) {
                const uint32_t bo =
                    SWZ64((wn * 32 + nt * 8 + b_row) * 64 + ks * 32 + b_kb);
                ldsm2(uBh + bo, bh[nt]);
                ldsm2(uBl + bo, bl[nt]);
            }
#pragma unroll
            for (int mt = 0; mt < 4; mt++) {
                uint32_t ah[4], al[4];
                const uint32_t ao =
                    SWZ64((wm * 64 + mt * 16 + a_row) * 64 + ks * 32 + a_kb);
                ldsm4(uAh + ao, ah);
                ldsm4(uAl + ao, al);
#pragma unroll
                for (int nt = 0; nt < 4; nt++) {
                    mma_bf16(c[mt][nt], ah, bh[nt]);
                    mma_bf16(c[mt][nt], ah, bl[nt]);
                    mma_bf16(c[mt][nt], al, bh[nt]);
                }
            }
        }
        __syncthreads();
    }

    const int gq = lane >> 2, tq = lane & 3;

    if (NOUT == 1) {
#pragma unroll
        for (int mt = 0; mt < 4; mt++) {
#pragma unroll
            for (int nt = 0; nt < 4; nt++) {
                const int row = m0 + wm * 64 + mt * 16 + gq;
                const int col = n0 + wn * 32 + nt * 8 + tq * 2;
                *(float2*)&Cout[(size_t)row * DM + col] =
                    make_float2(c[mt][nt][0], c[mt][nt][1]);
                *(float2*)&Cout[(size_t)(row + 8) * DM + col] =
                    make_float2(c[mt][nt][2], c[mt][nt][3]);
            }
        }
        return;
    }

    // ---- fused epilogue (NOUT == 3): l2norm (z<2) + split + [head][tok] ----
    const int z = blockIdx.z;
    __nv_bfloat16* H = (z == 0) ? qh : (z == 1) ? kh : vh;
    __nv_bfloat16* L = (z == 0) ? ql : (z == 1) ? kl : vl;

    float inv_[4][2];
#pragma unroll
    for (int mt = 0; mt < 4; mt++) { inv_[mt][0] = 1.0f; inv_[mt][1] = 1.0f; }

    if (z < 2) {
        // per-row sum of squares over this head's 64 cols (warp pair wn^1)
        float* rs = (float*)sm;  // [head(2)][rowlocal(128)][wnhalf(2)]
#pragma unroll
        for (int mt = 0; mt < 4; mt++) {
#pragma unroll
            for (int half = 0; half < 2; half++) {
                float s = 0.0f;
#pragma unroll
                for (int nt = 0; nt < 4; nt++) {
                    float a = c[mt][nt][half * 2 + 0];
                    float b = c[mt][nt][half * 2 + 1];
                    s += a * a + b * b;
                }
                s += __shfl_xor_sync(0xffffffffu, s, 1);
                s += __shfl_xor_sync(0xffffffffu, s, 2);
                if (tq == 0) {
                    const int rowl = wm * 64 + mt * 16 + gq + half * 8;
                    rs[(wn >> 1) * 256 + rowl * 2 + (wn & 1)] = s;
                }
            }
        }
        __syncthreads();
#pragma unroll
        for (int mt = 0; mt < 4; mt++) {
#pragma unroll
            for (int half = 0; half < 2; half++) {
                const int rowl = wm * 64 + mt * 16 + gq + half * 8;
                float ss = rs[(wn >> 1) * 256 + rowl * 2 + 0] +
                           rs[(wn >> 1) * 256 + rowl * 2 + 1];
                inv_[mt][half] = 1.0f / fmaxf(sqrtf(ss), 1e-12f);
            }
        }
    }

    const int head = (n0 >> 6) + (wn >> 1);
    const int dh = (wn & 1) * 32 + tq * 2;
    uint32_t* PH = (uint32_t*)H;
    uint32_t* PL = (uint32_t*)L;
#pragma unroll
    for (int mt = 0; mt < 4; mt++) {
        const int tok0 = m0 + wm * 64 + mt * 16 + gq;
        const float i0 = inv_[mt][0], i1 = inv_[mt][1];
#pragma unroll
        for (int nt = 0; nt < 4; nt++) {
            float a0 = c[mt][nt][0] * i0, a1 = c[mt][nt][1] * i0;
            float b0 = c[mt][nt][2] * i1, b1 = c[mt][nt][3] * i1;
            const size_t i0x =
                (((size_t)head * N_TOK + tok0) * DH + dh + nt * 8) >> 1;
            const size_t i1x = i0x + 4 * DH / 2 * 2;  // +8 rows = +8*64/2 u32
            PH[i0x] = pack2(a0, a1);
            PL[i0x] = pack2(a0 - bfr(a0), a1 - bfr(a1));
            PH[i1x] = pack2(b0, b1);
            PL[i1x] = pack2(b0 - bfr(b0), b1 - bfr(b1));
        }
    }
}

// ---------------------------------------------------------------------------
// Tensor-core causal flash attention. 1 CTA/SM, Q fragments hoisted.
// BOUNDED softmax: q,k are unit vectors so S = 8*cos ∈ [-8,8]; use the
// fixed shift m = 8 (exact softmax shift-invariance) -> no running max,
// no o-rescale, no per-tile reductions. l accumulates per-thread and is
// reduced once in the epilogue.
// ---------------------------------------------------------------------------
#define ATTN_SMEM (32768 + 2 * 32768)
#define SCALE_L2E 11.541560327111707f  /* 8 * log2(e) */

__global__ __launch_bounds__(256, 1) void attn_mma_kernel(
    const __nv_bfloat16* __restrict__ qh, const __nv_bfloat16* __restrict__ ql,
    const __nv_bfloat16* __restrict__ kh, const __nv_bfloat16* __restrict__ kl,
    const __nv_bfloat16* __restrict__ vh, const __nv_bfloat16* __restrict__ vl,
    __nv_bfloat16* __restrict__ oh, __nv_bfloat16* __restrict__ ol)
{
    extern __shared__ char sm[];
    const uint32_t sb = smem_u32(sm);
    const uint32_t uQh = sb, uQl = sb + 16384;

    const int tid = threadIdx.x, wid = tid >> 5, lane = tid & 31;
    const int h = blockIdx.y;
    const int qi = gridDim.x - 1 - blockIdx.x;
    const int q0 = qi * 128;
    const size_t hbase = (size_t)h * N_TOK * DH;  // bf16 elems

    // ---- load Q hi/lo tiles, swizzled ----
    {
        const char* gqh = (const char*)(qh + hbase + (size_t)q0 * DH);
        const char* gql = (const char*)(ql + hbase + (size_t)q0 * DH);
#pragma unroll
        for (int it = 0; it < 4; it++) {
            int idx = tid + 256 * it;
            int row = idx >> 3, ck = idx & 7;
            uint32_t so = SWZ128(row * 128 + ck * 16);
            *(uint4*)(sm + so) = *(const uint4*)(gqh + row * 128 + ck * 16);
            *(uint4*)(sm + 16384 + so) = *(const uint4*)(gql + row * 128 + ck * 16);
        }
    }

    const int kr0 = tid >> 3, kc0 = tid & 7;
    const int kr1 = (tid + 256) >> 3, kc1 = (tid + 256) & 7;
    const uint32_t kso0 = SWZ128(kr0 * 128 + kc0 * 16);
    const uint32_t kso1 = SWZ128(kr1 * 128 + kc1 * 16);

#define ATTN_ISSUE(jt, s) do {                                                  \
    const size_t _tb = hbase + (size_t)((jt) * 64) * DH;                        \
    const char* _kh = (const char*)(kh + _tb);                                  \
    const char* _kl = (const char*)(kl + _tb);                                  \
    const char* _vh = (const char*)(vh + _tb);                                  \
    const char* _vl = (const char*)(vl + _tb);                                  \
    const uint32_t _b = sb + 32768 + (s) * 32768;                               \
    cpa16(_b + kso0,          _kh + kr0 * 128 + kc0 * 16);                      \
    cpa16(_b + kso1,          _kh + kr1 * 128 + kc1 * 16);                      \
    cpa16(_b + 8192 + kso0,   _kl + kr0 * 128 + kc0 * 16);                      \
    cpa16(_b + 8192 + kso1,   _kl + kr1 * 128 + kc1 * 16);                      \
    cpa16(_b + 16384 + kso0,  _vh + kr0 * 128 + kc0 * 16);                      \
    cpa16(_b + 16384 + kso1,  _vh + kr1 * 128 + kc1 * 16);                      \
    cpa16(_b + 24576 + kso0,  _vl + kr0 * 128 + kc0 * 16);                      \
    cpa16(_b + 24576 + kso1,  _vl + kr1 * 128 + kc1 * 16);                      \
    CPA_COMMIT();                                                               \
} while (0)

    ATTN_ISSUE(0, 0);

    // ---- hoist Q fragments into registers (tile-invariant) ----
    __syncthreads();
    uint32_t qfh[4][4], qfl[4][4];
#pragma unroll
    for (int ks = 0; ks < 4; ks++) {
        const uint32_t ao = SWZ128(
            (wid * 16 + ((lane >> 3) & 1) * 8 + (lane & 7)) * 128 +
            ks * 32 + (lane >> 4) * 16);
        ldsm4(uQh + ao, qfh[ks]);
        ldsm4(uQl + ao, qfl[ks]);
    }

    float l_run[2] = {0.0f, 0.0f};
    float o[8][4] = {};

    const int row_lo = q0 + wid * 16 + (lane >> 2);
    const int njt = 2 * qi + 2;

    for (int jt = 0; jt < njt; jt++) {
        const int kv0 = jt * 64;
        CPA_WAIT0();
        __syncthreads();
        if (jt + 1 < njt) ATTN_ISSUE(jt + 1, (jt + 1) & 1);

        // warps 0-3 (rows q0..q0+63): last kv tile fully masked — skip
        if (wid < 4 && jt == njt - 1) continue;

        const uint32_t uKh = sb + 32768 + (jt & 1) * 32768;
        const uint32_t uKl = uKh + 8192;
        const uint32_t uVh = uKh + 16384;
        const uint32_t uVl = uKh + 24576;

        // ---- S = Qh*Kh + Qh*Kl + Ql*Kh  (m16 x n64, k=64) ----
        float c[8][4] = {};
#pragma unroll
        for (int ks = 0; ks < 4; ks++) {
#pragma unroll
            for (int np = 0; np < 4; np++) {
                uint32_t bh[4], bl[4];
                const uint32_t bo = SWZ128(
                    (np * 16 + (lane >> 4) * 8 + (lane & 7)) * 128 +
                    ks * 32 + ((lane >> 3) & 1) * 16);
                ldsm4(uKh + bo, bh);
                ldsm4(uKl + bo, bl);
                mma_bf16(c[2 * np + 0], qfh[ks], bh + 0);
                mma_bf16(c[2 * np + 0], qfh[ks], bl + 0);
                mma_bf16(c[2 * np + 0], qfl[ks], bh + 0);
                mma_bf16(c[2 * np + 1], qfh[ks], bh + 2);
                mma_bf16(c[2 * np + 1], qfh[ks], bl + 2);
                mma_bf16(c[2 * np + 1], qfl[ks], bh + 2);
            }
        }

        // ---- bounded softmax: p = exp2(SCALE*(s-1)), causal-masked to 0 ----
#pragma unroll
        for (int nt = 0; nt < 8; nt++) {
#pragma unroll
            for (int j = 0; j < 4; j++) {
                const int half = j >> 1, i = j & 1;
                const int key = kv0 + nt * 8 + (lane & 3) * 2 + i;
                float pv = exp2f(fmaf(c[nt][j], SCALE_L2E, -SCALE_L2E));
                pv = (key > row_lo + 8 * half) ? 0.0f : pv;
                c[nt][j] = pv;
                l_run[half] += pv;
            }
        }

        // ---- PV interleaved with pack (short ph/pl live range) ----
#pragma unroll
        for (int kt = 0; kt < 4; kt++) {
            uint32_t ph[4], pl[4];
            {
                const float* e = c[2 * kt];
                const float* f = c[2 * kt + 1];
                ph[0] = pack2(e[0], e[1]);
                ph[1] = pack2(e[2], e[3]);
                ph[2] = pack2(f[0], f[1]);
                ph[3] = pack2(f[2], f[3]);
                pl[0] = pack2(e[0] - bfr(e[0]), e[1] - bfr(e[1]));
                pl[1] = pack2(e[2] - bfr(e[2]), e[3] - bfr(e[3]));
                pl[2] = pack2(f[0] - bfr(f[0]), f[1] - bfr(f[1]));
                pl[3] = pack2(f[2] - bfr(f[2]), f[3] - bfr(f[3]));
            }
#pragma unroll
            for (int dp = 0; dp < 4; dp++) {
                uint32_t vhf[4], vlf[4];
                const uint32_t vo = SWZ128(
                    (kt * 16 + (lane & 15)) * 128 +
                    dp * 32 + (lane >> 4) * 16);
                ldsm4t(uVh + vo, vhf);
                ldsm4t(uVl + vo, vlf);
                mma_bf16(o[2 * dp + 0], ph, vhf + 0);
                mma_bf16(o[2 * dp + 0], ph, vlf + 0);
                mma_bf16(o[2 * dp + 0], pl, vhf + 0);
                mma_bf16(o[2 * dp + 1], ph, vhf + 2);
                mma_bf16(o[2 * dp + 1], ph, vlf + 2);
                mma_bf16(o[2 * dp + 1], pl, vhf + 2);
            }
        }
    }

    // ---- epilogue: reduce l across quad, O /= l, split, write ----
#pragma unroll
    for (int half = 0; half < 2; half++) {
        l_run[half] += __shfl_xor_sync(0xffffffffu, l_run[half], 1);
        l_run[half] += __shfl_xor_sync(0xffffffffu, l_run[half], 2);
    }
    const float inv0 = 1.0f / l_run[0];
    const float inv1 = 1.0f / l_run[1];
    uint32_t* poh = (uint32_t*)oh;
    uint32_t* pol = (uint32_t*)ol;
#pragma unroll
    for (int dt = 0; dt < 8; dt++) {
        const int col = h * DH + dt * 8 + (lane & 3) * 2;
        float a0 = o[dt][0] * inv0, a1 = o[dt][1] * inv0;
        float b0 = o[dt][2] * inv1, b1 = o[dt][3] * inv1;
        const size_t i0 = ((size_t)row_lo * DM + col) >> 1;
        const size_t i1 = ((size_t)(row_lo + 8) * DM + col) >> 1;
        poh[i0] = pack2(a0, a1);
        pol[i0] = pack2(a0 - bfr(a0), a1 - bfr(a1));
        poh[i1] = pack2(b0, b1);
        pol[i1] = pack2(b0 - bfr(b0), b1 - bfr(b1));
    }
}

// ---------------------------------------------------------------------------
extern "C" void kernel_launch(void* const* d_in, const int* in_sizes, int n_in,
                              void* d_out, int out_size)
{
    const float* x  = (const float*)d_in[0];
    const float* Wq = (const float*)d_in[1];
    const float* Wk = (const float*)d_in[2];
    const float* Wv = (const float*)d_in[3];
    const float* Wo = (const float*)d_in[4];
    float* out = (float*)d_out;

    __nv_bfloat16 *xh, *xl, *oh, *ol, *wth, *wtl;
    __nv_bfloat16 *qh, *ql, *kh, *kl, *vh, *vl;
    cudaGetSymbolAddress((void**)&xh, g_xh);
    cudaGetSymbolAddress((void**)&xl, g_xl);
    cudaGetSymbolAddress((void**)&oh, g_oh);
    cudaGetSymbolAddress((void**)&ol, g_ol);
    cudaGetSymbolAddress((void**)&wth, g_wth);
    cudaGetSymbolAddress((void**)&wtl, g_wtl);
    cudaGetSymbolAddress((void**)&qh, g_qh);
    cudaGetSymbolAddress((void**)&ql, g_ql);
    cudaGetSymbolAddress((void**)&kh, g_kh);
    cudaGetSymbolAddress((void**)&kl, g_kl);
    cudaGetSymbolAddress((void**)&vh, g_vh);
    cudaGetSymbolAddress((void**)&vl, g_vl);

    cudaFuncSetAttribute(gemm_mma_kernel<3>,
                         cudaFuncAttributeMaxDynamicSharedMemorySize, GEMM_SMEM);
    cudaFuncSetAttribute(gemm_mma_kernel<1>,
                         cudaFuncAttributeMaxDynamicSharedMemorySize, GEMM_SMEM);
    cudaFuncSetAttribute(attn_mma_kernel,
                         cudaFuncAttributeMaxDynamicSharedMemorySize, ATTN_SMEM);

    const int nvec = N_TOK * DM / 4;

    split_kernel<<<nvec / 256, 256>>>(x, xh, xl);
    tsplit_kernel<<<dim3(32, 32, 4), dim3(32, 8)>>>(Wq, Wk, Wv, Wo, wth, wtl);
    // merged q/k/v projection with fused l2norm + split epilogue
    gemm_mma_kernel<3><<<dim3(DM / 128, N_TOK / 128, 3), 256, GEMM_SMEM>>>(
        xh, xl, wth, wtl, nullptr, qh, ql, kh, kl, vh, vl);
    attn_mma_kernel<<<dim3(N_TOK / 128, NHEADS), 256, ATTN_SMEM>>>(
        qh, ql, kh, kl, vh, vl, oh, ol);
    gemm_mma_kernel<1><<<dim3(DM / 128, N_TOK / 128, 1), 256, GEMM_SMEM>>>(
        oh, ol, wth + 3 * (size_t)DM * DM, wtl + 3 * (size_t)DM * DM, out,
        nullptr, nullptr, nullptr, nullptr, nullptr, nullptr);
}